// round 8
// baseline (speedup 1.0000x reference)
#include <cuda_runtime.h>
#include <cuda_bf16.h>
#include <cuda_fp16.h>
#include <math.h>

// StatEncoder — persistent mma.sync fp16 GRU, plain sm_100 target.
//   SINGLE-PASS fp16: D[M,96+fold] = A[M,272] @ W^T, m16n8k16 f16 with f32
//   accum. A = fp16(h) (state itself stays fp32 in registers -> rounding does
//   NOT compound), W = fp16(W). 17 K-chunks: 0-15 = h (K=256), 16 = x-fold
//   chunk (x features k0..7, const-1 at k8 carrying r/z/hn biases; hn rows
//   have zero x-weights). inn gate (x-only) stays fp32 SIMT in the epilogue.
//   Per-warp producer flags (red.release.add / ld.acquire), own chunk kept in
//   registers, foreign chunks prefetched through a 4-slot ring.

#define Bsz   2048
#define Wlen  128
#define Fin   8
#define Hdim  256

#define N_WF   104448          // 8c x 17q x 12nf x 64 words
#define N_WXN  2048            // 8c x 32jl x 8 (Wih_n for inn)
#define N_BIN  256
#define N_HZ0  262144          // parity-0 A plane words
#define N_WPT  131072
#define NFLAG  2048            // [bt(32)][wr(4)... fbase = bt*64+wr*2 + c*8+wc]

// dynamic smem layout (bytes)
#define SMW_BYTES 52224        // 13056 words
#define SM_WXN    52224
#define SM_BIN    53248
#define SM_TOTAL  54272

// ---- static device scratch ----
__device__ __align__(256) unsigned g_wfrag[N_WF];
__device__ __align__(256) float    g_wxn[N_WXN];
__device__ __align__(256) float    g_bin[N_BIN];
// [par][rb(128)][q(16)][128 words]  (single fp16 plane)
__device__ __align__(256) unsigned g_hA[2 * 128 * 16 * 128];
__device__ __align__(256) float    g_hfinal[Bsz * Hdim];
__device__ __align__(256) float    g_Wpt[N_WPT];
__device__ int g_flag[NFLAG];

// ---- helpers ----
static __device__ __forceinline__ unsigned f2h2(float a, float b) {
    return (unsigned)__half_as_ushort(__float2half_rn(a)) |
           ((unsigned)__half_as_ushort(__float2half_rn(b)) << 16);
}
static __device__ __forceinline__ unsigned ld_acq(const int* p) {
    unsigned v;
    asm volatile("ld.acquire.gpu.global.u32 %0, [%1];" : "=r"(v) : "l"(p) : "memory");
    return v;
}
static __device__ __forceinline__ void red_rel_add(int* p, unsigned v) {
    asm volatile("red.release.gpu.global.add.u32 [%0], %1;" :: "l"(p), "r"(v) : "memory");
}

#define MMAH(d, a, b0v, b1v)                                                   \
    asm volatile(                                                              \
        "mma.sync.aligned.m16n8k16.row.col.f32.f16.f16.f32 "                   \
        "{%0,%1,%2,%3}, {%4,%5,%6,%7}, {%8,%9}, {%0,%1,%2,%3};"                \
        : "+f"(d[0]), "+f"(d[1]), "+f"(d[2]), "+f"(d[3])                       \
        : "r"(a.x), "r"(a.y), "r"(a.z), "r"(a.w), "r"(b0v), "r"(b1v))

// ---------------- prep ------------------------------------------------------
#define N_PREP (N_WF + N_WXN + N_BIN + N_HZ0 + NFLAG + N_WPT)

__global__ void prep_kernel(const float* __restrict__ Whh_f,
                            const float* __restrict__ Wih_f,
                            const float* __restrict__ bih_f,
                            const float* __restrict__ bhh_f,
                            const float* __restrict__ Wp) {
    int idx = blockIdx.x * blockDim.x + threadIdx.x;
    if (idx < N_WF) {
        int c  = idx / 13056, r = idx % 13056;
        int q  = r / 768,     r3 = r % 768;
        int nfg = r3 / 64,    r4 = r3 % 64;
        int L  = r4 >> 1,     ws = r4 & 1;
        int n  = nfg * 8 + (L >> 2);
        int wc = n / 48, r5 = n % 48;
        int gate = r5 / 16;                 // 0=r, 1=z, 2=hn
        int jl = wc * 16 + (r5 % 16);
        int j  = c * 32 + jl;
        float v0, v1;
        if (q < 16) {
            int k0 = q * 16 + ((L & 3) << 1) + ws * 8;
            v0 = Whh_f[(gate * 256 + j) * 256 + k0];
            v1 = Whh_f[(gate * 256 + j) * 256 + k0 + 1];
        } else {
            // x-fold chunk: k 0..7 = Wih (r,z only), k8 = combined bias, else 0
            int kb = ((L & 3) << 1) + ws * 8;
            float e[2];
#pragma unroll
            for (int u = 0; u < 2; u++) {
                int kk = kb + u;
                float v = 0.0f;
                if (kk < 8) {
                    if (gate < 2) v = Wih_f[(gate * 256 + j) * 8 + kk];
                } else if (kk == 8) {
                    if (gate == 0)      v = bih_f[j] + bhh_f[j];
                    else if (gate == 1) v = bih_f[256 + j] + bhh_f[256 + j];
                    else                v = bhh_f[512 + j];
                }
                e[u] = v;
            }
            v0 = e[0]; v1 = e[1];
        }
        g_wfrag[idx] = f2h2(v0, v1);
    } else if (idx < N_WF + N_WXN) {
        int i = idx - N_WF;
        int c = i / 256, r = i % 256;
        int jl = r / 8, e = r % 8;
        int j = c * 32 + jl;
        g_wxn[i] = Wih_f[(512 + j) * 8 + e];
    } else if (idx < N_WF + N_WXN + N_BIN) {
        int j = idx - N_WF - N_WXN;
        g_bin[j] = bih_f[512 + j];
    } else if (idx < N_WF + N_WXN + N_BIN + N_HZ0) {
        g_hA[idx - N_WF - N_WXN - N_BIN] = 0u;     // parity-0 plane = h(0) = 0
    } else if (idx < N_WF + N_WXN + N_BIN + N_HZ0 + NFLAG) {
        g_flag[idx - N_WF - N_WXN - N_BIN - N_HZ0] = 0;
    } else if (idx < N_PREP) {
        int i = idx - N_WF - N_WXN - N_BIN - N_HZ0 - NFLAG;
        int m = i / Hdim, j = i - m * Hdim;
        g_Wpt[i] = Wp[j * (2 * Hdim) + m];
    }
}

// ---------------- persistent GRU -------------------------------------------
template<int MPW>
__global__ void __launch_bounds__(256, 2)
gru_persist(const float* __restrict__ x) {
    extern __shared__ unsigned smem[];
    const int tid = threadIdx.x;
    const int bt = blockIdx.x >> 3;     // batch-tile group
    const int c  = blockIdx.x & 7;      // column group 0..7

    // resident weights
    {
        const uint4* src = (const uint4*)(g_wfrag + c * 13056);
        uint4* dst = (uint4*)smem;
        for (int i = tid; i < 3264; i += 256) dst[i] = src[i];
        float* wxd = (float*)((char*)smem + SM_WXN);
        const float* wxs = g_wxn + c * 256;
        for (int i = tid; i < 256; i += 256) wxd[i] = wxs[i];
        float* bd = (float*)((char*)smem + SM_BIN);
        for (int i = tid; i < 256; i += 256) bd[i] = g_bin[i];
    }
    __syncthreads();

    const int w  = tid >> 5, L = tid & 31;
    const int wr = w >> 1;              // warp row-group
    const int wc = w & 1;               // N col half (16 jl)
    const unsigned* Wf = smem;          // fp16 B frags, 17 chunks
    const float* swxn = (const float*)((char*)smem + SM_WXN);
    const float* sbin = (const float*)((char*)smem + SM_BIN);
    const int qw   = 2 * c + wc;        // K-chunk this warp produces
    const int rbw  = bt * (4 * MPW) + wr * MPW;
    const int fbase = bt * 64 + wr * 2;
    const int fown  = fbase + c * 8 + wc;

    float hold[MPW * 8];
#pragma unroll
    for (int i = 0; i < MPW * 8; i++) hold[i] = 0.0f;
    uint4 own_fa[MPW];
#pragma unroll
    for (int m = 0; m < MPW; m++) own_fa[m] = make_uint4(0u, 0u, 0u, 0u);

    for (int t = 0; t < Wlen; t++) {
        const int par = t & 1;
        const unsigned thr = 32u * (unsigned)t;
        float acc[MPW][6][4];
#pragma unroll
        for (int m = 0; m < MPW; m++)
#pragma unroll
            for (int nf = 0; nf < 6; nf++)
#pragma unroll
                for (int u = 0; u < 4; u++) acc[m][nf][u] = 0.0f;

        // x(t): load + build the chunk-16 A fragment (also reused for xn)
        float4 xv[MPW * 2][2];
        uint4 xfrag[MPW];
#pragma unroll
        for (int m = 0; m < MPW; m++) {
#pragma unroll
            for (int rh = 0; rh < 2; rh++) {
                const int row = (rbw + m) * 16 + (L >> 2) + 8 * rh;
                const float4* xp = (const float4*)(x + (size_t)row * (Wlen * Fin) + t * Fin);
                xv[m * 2 + rh][0] = __ldg(xp);
                xv[m * 2 + rh][1] = __ldg(xp + 1);
            }
            const float* f0 = (const float*)&xv[m * 2 + 0][0];
            const float* f1 = (const float*)&xv[m * 2 + 1][0];
            const int c0 = (L & 3) << 1;
            const unsigned one = ((L & 3) == 0) ? f2h2(1.0f, 0.0f) : 0u;
            xfrag[m].x = f2h2(f0[c0], f0[c0 + 1]);
            xfrag[m].y = f2h2(f1[c0], f1[c0 + 1]);
            xfrag[m].z = one;
            xfrag[m].w = one;
        }

        const unsigned* Ah = g_hA + ((size_t)par * 128 + rbw) * 2048;

        // prefetch ring: first 2 foreign chunks
        uint4 F[4][MPW];
#pragma unroll
        for (int d = 0; d < 2; d++) {
            const int qn = (qw + 1 + d) & 15;
            const int fidx = fbase + (qn >> 1) * 8 + (qn & 1);
            long guard = 0;
            while (ld_acq(&g_flag[fidx]) < thr && guard < 1000000000L) guard++;
#pragma unroll
            for (int m = 0; m < MPW; m++)
                F[d][m] = __ldcg((const uint4*)(Ah + (size_t)m * 2048 + qn * 128) + L);
        }

        // own chunk (registers)
        {
            const int bbase = (qw * 12 + wc * 6) * 64 + (L << 1);
#pragma unroll
            for (int nf = 0; nf < 6; nf++) {
                uint2 bb = *(const uint2*)(Wf + bbase + nf * 64);
#pragma unroll
                for (int m = 0; m < MPW; m++) MMAH(acc[m][nf], own_fa[m], bb.x, bb.y);
            }
        }
        // prefetch foreign 2,3
#pragma unroll
        for (int d = 2; d < 4; d++) {
            const int qn = (qw + 1 + d) & 15;
            const int fidx = fbase + (qn >> 1) * 8 + (qn & 1);
            long guard = 0;
            while (ld_acq(&g_flag[fidx]) < thr && guard < 1000000000L) guard++;
#pragma unroll
            for (int m = 0; m < MPW; m++)
                F[d][m] = __ldcg((const uint4*)(Ah + (size_t)m * 2048 + qn * 128) + L);
        }
        // x-fold chunk (q = 16)
        {
            const int bbase = (16 * 12 + wc * 6) * 64 + (L << 1);
#pragma unroll
            for (int nf = 0; nf < 6; nf++) {
                uint2 bb = *(const uint2*)(Wf + bbase + nf * 64);
#pragma unroll
                for (int m = 0; m < MPW; m++) MMAH(acc[m][nf], xfrag[m], bb.x, bb.y);
            }
        }
        // 15 foreign chunks, 4-deep ring
#pragma unroll 3
        for (int fi = 0; fi < 15; fi++) {
            uint4 cf[MPW];
#pragma unroll
            for (int m = 0; m < MPW; m++) cf[m] = F[fi & 3][m];
            if (fi + 4 < 15) {
                const int qn = (qw + 5 + fi) & 15;
                const int fidx = fbase + (qn >> 1) * 8 + (qn & 1);
                long guard = 0;
                while (ld_acq(&g_flag[fidx]) < thr && guard < 1000000000L) guard++;
#pragma unroll
                for (int m = 0; m < MPW; m++)
                    F[fi & 3][m] = __ldcg((const uint4*)(Ah + (size_t)m * 2048 + qn * 128) + L);
            }
            const int q = (qw + 1 + fi) & 15;
            const int bbase = (q * 12 + wc * 6) * 64 + (L << 1);
#pragma unroll
            for (int nf = 0; nf < 6; nf++) {
                uint2 bb = *(const uint2*)(Wf + bbase + nf * 64);
#pragma unroll
                for (int m = 0; m < MPW; m++) MMAH(acc[m][nf], cf[m], bb.x, bb.y);
            }
        }

        // ---- epilogue: inn (x-only, fp32) + gates + h update + frag store --
        const int pw = par ^ 1;
#pragma unroll
        for (int m = 0; m < MPW; m++) {
            const int rb = rbw + m;
            unsigned whi[4];
#pragma unroll
            for (int rh = 0; rh < 2; rh++) {
                const float* x8 = (const float*)&xv[m * 2 + rh][0];
#pragma unroll
                for (int fp = 0; fp < 2; fp++) {
                    float hpair[2];
#pragma unroll
                    for (int e = 0; e < 2; e++) {
                        const int jl = wc * 16 + 2 * (L & 3) + 8 * fp + e;
                        const int j  = c * 32 + jl;
                        const float* wj = swxn + jl * 8;
                        float xn = sbin[j];
#pragma unroll
                        for (int u = 0; u < 8; u++) xn = fmaf(x8[u], wj[u], xn);
                        const int ci = rh * 2 + e;
                        float rp  = acc[m][fp][ci];          // bias+x folded
                        float zp  = acc[m][2 + fp][ci];
                        float hnv = acc[m][4 + fp][ci];      // includes bhn
                        float r = __fdividef(1.0f, 1.0f + __expf(-rp));
                        float z = __fdividef(1.0f, 1.0f + __expf(-zp));
                        float an = xn + r * hnv;
                        an = fminf(fmaxf(an, -15.0f), 15.0f);
                        float e2 = __expf(-2.0f * an);
                        float n  = (1.0f - e2) * __fdividef(1.0f, 1.0f + e2);
                        const int hidx = ((m * 2 + rh) * 2 + fp) * 2 + e;
                        float h = (1.0f - z) * n + z * hold[hidx];
                        hold[hidx] = h;
                        hpair[e] = h;
                    }
                    whi[rh + 2 * fp] = f2h2(hpair[0], hpair[1]);
                }
            }
            own_fa[m] = make_uint4(whi[0], whi[1], whi[2], whi[3]);
            *(((uint4*)(g_hA + ((size_t)pw * 128 + rb) * 2048 + qw * 128)) + L) = own_fa[m];
        }
        red_rel_add(&g_flag[fown], 1u);
    }

    // final h -> plain layout
#pragma unroll
    for (int m = 0; m < MPW; m++)
#pragma unroll
        for (int rh = 0; rh < 2; rh++) {
            const int row = (rbw + m) * 16 + (L >> 2) + 8 * rh;
#pragma unroll
            for (int fp = 0; fp < 2; fp++)
#pragma unroll
                for (int e = 0; e < 2; e++) {
                    const int jl = wc * 16 + 2 * (L & 3) + 8 * fp + e;
                    const int hidx = ((m * 2 + rh) * 2 + fp) * 2 + e;
                    g_hfinal[(size_t)row * 256 + c * 32 + jl] = hold[hidx];
                }
        }
}

// ---------------- head: h_bwd + projection + GELU + LayerNorm ---------------
__global__ void __launch_bounds__(256)
head_kernel(const float* __restrict__ x,
            const float* __restrict__ Wih_b,
            const float* __restrict__ bih_b,
            const float* __restrict__ bhh_b,
            const float* __restrict__ bp,
            const float* __restrict__ gamma,
            const float* __restrict__ beta,
            float* __restrict__ out) {
    __shared__ float hf[8][Hdim];
    __shared__ float hb[8][Hdim];
    __shared__ float ys[8][Hdim];
    __shared__ float xs[8][Fin];

    const int tx = threadIdx.x;
    const int b0 = blockIdx.x * 8;

    for (int idx = tx; idx < 8 * Hdim; idx += 256) {
        int r = idx >> 8, k = idx & 255;
        hf[r][k] = g_hfinal[(size_t)(b0 + r) * Hdim + k];
    }
    if (tx < 64) {
        int r = tx >> 3, cc = tx & 7;
        xs[r][cc] = x[(size_t)(b0 + r) * (Wlen * Fin) + (Wlen - 1) * Fin + cc];
    }
    __syncthreads();

    {   // backward cell at h0 = 0
        const int j = tx;
        float wr[Fin], wz[Fin], wn[Fin];
#pragma unroll
        for (int cc = 0; cc < Fin; cc++) {
            wr[cc] = Wih_b[j * Fin + cc];
            wz[cc] = Wih_b[(256 + j) * Fin + cc];
            wn[cc] = Wih_b[(512 + j) * Fin + cc];
        }
        const float bir = bih_b[j],       bhr = bhh_b[j];
        const float biz = bih_b[256 + j], bhz = bhh_b[256 + j];
        const float bin = bih_b[512 + j], bhn = bhh_b[512 + j];
#pragma unroll
        for (int r8 = 0; r8 < 8; r8++) {
            float gr = bir + bhr, gz = biz + bhz, gn = bin;
#pragma unroll
            for (int cc = 0; cc < Fin; cc++) {
                float xvv = xs[r8][cc];
                gr = fmaf(xvv, wr[cc], gr);
                gz = fmaf(xvv, wz[cc], gz);
                gn = fmaf(xvv, wn[cc], gn);
            }
            float r = 1.0f / (1.0f + __expf(-gr));
            float z = 1.0f / (1.0f + __expf(-gz));
            float an = gn + r * bhn;
            an = fminf(fmaxf(an, -15.0f), 15.0f);
            float e = __expf(-2.0f * an);
            float n = (1.0f - e) / (1.0f + e);
            hb[r8][j] = (1.0f - z) * n;
        }
    }
    __syncthreads();

    {   // projection + exact GELU
        const int j = tx;
#pragma unroll
        for (int r8 = 0; r8 < 8; r8++) {
            float acc = bp[j];
#pragma unroll 4
            for (int k = 0; k < Hdim; k++)
                acc = fmaf(hf[r8][k], g_Wpt[k * Hdim + j], acc);
#pragma unroll 4
            for (int k = 0; k < Hdim; k++)
                acc = fmaf(hb[r8][k], g_Wpt[(Hdim + k) * Hdim + j], acc);
            ys[r8][j] = 0.5f * acc * (1.0f + erff(acc * 0.70710678118654752f));
        }
    }
    __syncthreads();

    const int w = tx >> 5, l = tx & 31;
    float s1 = 0.f, s2 = 0.f;
#pragma unroll
    for (int m = 0; m < 8; m++) {
        float v = ys[w][l + 32 * m];
        s1 += v; s2 += v * v;
    }
#pragma unroll
    for (int o = 16; o > 0; o >>= 1) {
        s1 += __shfl_xor_sync(0xffffffffu, s1, o);
        s2 += __shfl_xor_sync(0xffffffffu, s2, o);
    }
    const float mu  = s1 * (1.0f / 256.0f);
    const float var = s2 * (1.0f / 256.0f) - mu * mu;
    const float inv = rsqrtf(var + 1e-5f);
#pragma unroll
    for (int m = 0; m < 8; m++) {
        int col = l + 32 * m;
        float v = (ys[w][col] - mu) * inv;
        out[(size_t)(b0 + w) * Hdim + col] = v * gamma[col] + beta[col];
    }
}

// ---------------------------------------------------------------------------
extern "C" void kernel_launch(void* const* d_in, const int* in_sizes, int n_in,
                              void* d_out, int out_size) {
    const float* x     = (const float*)d_in[0];
    const float* Wih_f = (const float*)d_in[1];
    const float* Whh_f = (const float*)d_in[2];
    const float* bih_f = (const float*)d_in[3];
    const float* bhh_f = (const float*)d_in[4];
    const float* Wih_b = (const float*)d_in[5];
    /* Whh_b = d_in[6] unused: backward cell has h0 = 0 */
    const float* bih_b = (const float*)d_in[7];
    const float* bhh_b = (const float*)d_in[8];
    const float* Wp    = (const float*)d_in[9];
    const float* bp    = (const float*)d_in[10];
    const float* gamma = (const float*)d_in[11];
    const float* beta  = (const float*)d_in[12];
    float* out = (float*)d_out;

    cudaFuncSetAttribute(gru_persist<1>, cudaFuncAttributeMaxDynamicSharedMemorySize, SM_TOTAL);
    cudaFuncSetAttribute(gru_persist<2>, cudaFuncAttributeMaxDynamicSharedMemorySize, SM_TOTAL);

    int dev = 0, sms = 0, nb = 0;
    cudaGetDevice(&dev);
    cudaDeviceGetAttribute(&sms, cudaDevAttrMultiProcessorCount, dev);
    cudaOccupancyMaxActiveBlocksPerMultiprocessor(&nb, gru_persist<1>, 256, SM_TOTAL);

    prep_kernel<<<(N_PREP + 255) / 256, 256>>>(Whh_f, Wih_f, bih_f, bhh_f, Wp);

    if ((long)nb * sms >= 256)
        gru_persist<1><<<256, 256, SM_TOTAL>>>(x);
    else
        gru_persist<2><<<128, 256, SM_TOTAL>>>(x);

    head_kernel<<<Bsz / 8, 256>>>(x, Wih_b, bih_b, bhh_b, bp, gamma, beta, out);
}

// round 9
// speedup vs baseline: 1.3857x; 1.3857x over previous
#include <cuda_runtime.h>
#include <cuda_bf16.h>
#include <cuda_fp16.h>
#include <math.h>

// StatEncoder — persistent mma.sync fp16 GRU, plain sm_100 target.
//   Single-pass fp16 (R8 math, rel_err 5e-5): D = A[M,272] @ W^T, 17 K-chunks
//   (16 h-chunks + x-fold chunk with biases at k8). inn gate fp32 SIMT.
//   R9 structure: per step, ONE 16-flag group wait (ballot), then all 15
//   foreign A-fragment LDG.128s issued back-to-back (MLP=15) hidden under
//   own-chunk + x-fold MMAs; then 15 foreign chunks' MMAs in load order.

#define Bsz   2048
#define Wlen  128
#define Fin   8
#define Hdim  256

#define N_WF   104448          // 8c x 17q x 12nf x 64 words
#define N_WXN  2048            // 8c x 32jl x 8 (Wih_n for inn)
#define N_BIN  256
#define N_HZ0  262144          // parity-0 A plane words
#define N_WPT  131072
#define NFLAG  2048

// dynamic smem layout (bytes)
#define SM_WXN    52224
#define SM_BIN    53248
#define SM_TOTAL  54272

// ---- static device scratch ----
__device__ __align__(256) unsigned g_wfrag[N_WF];
__device__ __align__(256) float    g_wxn[N_WXN];
__device__ __align__(256) float    g_bin[N_BIN];
// [par][rb(128)][q(16)][128 words]  (single fp16 plane)
__device__ __align__(256) unsigned g_hA[2 * 128 * 16 * 128];
__device__ __align__(256) float    g_hfinal[Bsz * Hdim];
__device__ __align__(256) float    g_Wpt[N_WPT];
__device__ int g_flag[NFLAG];

// ---- helpers ----
static __device__ __forceinline__ unsigned f2h2(float a, float b) {
    return (unsigned)__half_as_ushort(__float2half_rn(a)) |
           ((unsigned)__half_as_ushort(__float2half_rn(b)) << 16);
}
static __device__ __forceinline__ unsigned ld_acq(const int* p) {
    unsigned v;
    asm volatile("ld.acquire.gpu.global.u32 %0, [%1];" : "=r"(v) : "l"(p) : "memory");
    return v;
}
static __device__ __forceinline__ void red_rel_add(int* p, unsigned v) {
    asm volatile("red.release.gpu.global.add.u32 [%0], %1;" :: "l"(p), "r"(v) : "memory");
}

#define MMAH(d, a, b0v, b1v)                                                   \
    asm volatile(                                                              \
        "mma.sync.aligned.m16n8k16.row.col.f32.f16.f16.f32 "                   \
        "{%0,%1,%2,%3}, {%4,%5,%6,%7}, {%8,%9}, {%0,%1,%2,%3};"                \
        : "+f"(d[0]), "+f"(d[1]), "+f"(d[2]), "+f"(d[3])                       \
        : "r"(a.x), "r"(a.y), "r"(a.z), "r"(a.w), "r"(b0v), "r"(b1v))

// one K-chunk = 6 MMAs against SMEM-resident B fragments
#define MMA_CHUNK(qidx, afr)                                                   \
    {                                                                          \
        const int bb_ = ((qidx) * 12 + wc * 6) * 64 + (L << 1);                \
        _Pragma("unroll")                                                      \
        for (int nf_ = 0; nf_ < 6; nf_++) {                                    \
            uint2 bw_ = *(const uint2*)(Wf + bb_ + nf_ * 64);                  \
            _Pragma("unroll")                                                  \
            for (int m_ = 0; m_ < MPW; m_++)                                   \
                MMAH(acc[m_][nf_], (afr)[m_], bw_.x, bw_.y);                   \
        }                                                                      \
    }

// ---------------- prep ------------------------------------------------------
#define N_PREP (N_WF + N_WXN + N_BIN + N_HZ0 + NFLAG + N_WPT)

__global__ void prep_kernel(const float* __restrict__ Whh_f,
                            const float* __restrict__ Wih_f,
                            const float* __restrict__ bih_f,
                            const float* __restrict__ bhh_f,
                            const float* __restrict__ Wp) {
    int idx = blockIdx.x * blockDim.x + threadIdx.x;
    if (idx < N_WF) {
        int c  = idx / 13056, r = idx % 13056;
        int q  = r / 768,     r3 = r % 768;
        int nfg = r3 / 64,    r4 = r3 % 64;
        int L  = r4 >> 1,     ws = r4 & 1;
        int n  = nfg * 8 + (L >> 2);
        int wc = n / 48, r5 = n % 48;
        int gate = r5 / 16;                 // 0=r, 1=z, 2=hn
        int jl = wc * 16 + (r5 % 16);
        int j  = c * 32 + jl;
        float v0, v1;
        if (q < 16) {
            int k0 = q * 16 + ((L & 3) << 1) + ws * 8;
            v0 = Whh_f[(gate * 256 + j) * 256 + k0];
            v1 = Whh_f[(gate * 256 + j) * 256 + k0 + 1];
        } else {
            int kb = ((L & 3) << 1) + ws * 8;
            float e[2];
#pragma unroll
            for (int u = 0; u < 2; u++) {
                int kk = kb + u;
                float v = 0.0f;
                if (kk < 8) {
                    if (gate < 2) v = Wih_f[(gate * 256 + j) * 8 + kk];
                } else if (kk == 8) {
                    if (gate == 0)      v = bih_f[j] + bhh_f[j];
                    else if (gate == 1) v = bih_f[256 + j] + bhh_f[256 + j];
                    else                v = bhh_f[512 + j];
                }
                e[u] = v;
            }
            v0 = e[0]; v1 = e[1];
        }
        g_wfrag[idx] = f2h2(v0, v1);
    } else if (idx < N_WF + N_WXN) {
        int i = idx - N_WF;
        int c = i / 256, r = i % 256;
        int jl = r / 8, e = r % 8;
        int j = c * 32 + jl;
        g_wxn[i] = Wih_f[(512 + j) * 8 + e];
    } else if (idx < N_WF + N_WXN + N_BIN) {
        int j = idx - N_WF - N_WXN;
        g_bin[j] = bih_f[512 + j];
    } else if (idx < N_WF + N_WXN + N_BIN + N_HZ0) {
        g_hA[idx - N_WF - N_WXN - N_BIN] = 0u;     // parity-0 plane = h(0) = 0
    } else if (idx < N_WF + N_WXN + N_BIN + N_HZ0 + NFLAG) {
        g_flag[idx - N_WF - N_WXN - N_BIN - N_HZ0] = 0;
    } else if (idx < N_PREP) {
        int i = idx - N_WF - N_WXN - N_BIN - N_HZ0 - NFLAG;
        int m = i / Hdim, j = i - m * Hdim;
        g_Wpt[i] = Wp[j * (2 * Hdim) + m];
    }
}

// ---------------- persistent GRU -------------------------------------------
template<int MPW>
__global__ void __launch_bounds__(256, 2)
gru_persist(const float* __restrict__ x) {
    extern __shared__ unsigned smem[];
    const int tid = threadIdx.x;
    const int bt = blockIdx.x >> 3;     // batch-tile group
    const int c  = blockIdx.x & 7;      // column group 0..7

    // resident weights
    {
        const uint4* src = (const uint4*)(g_wfrag + c * 13056);
        uint4* dst = (uint4*)smem;
        for (int i = tid; i < 3264; i += 256) dst[i] = src[i];
        float* wxd = (float*)((char*)smem + SM_WXN);
        const float* wxs = g_wxn + c * 256;
        for (int i = tid; i < 256; i += 256) wxd[i] = wxs[i];
        float* bd = (float*)((char*)smem + SM_BIN);
        for (int i = tid; i < 256; i += 256) bd[i] = g_bin[i];
    }
    __syncthreads();

    const int w  = tid >> 5, L = tid & 31;
    const int wr = w >> 1;              // warp row-group
    const int wc = w & 1;               // N col half (16 jl)
    const unsigned* Wf = smem;          // fp16 B frags, 17 chunks
    const float* swxn = (const float*)((char*)smem + SM_WXN);
    const float* sbin = (const float*)((char*)smem + SM_BIN);
    const int qw   = 2 * c + wc;        // K-chunk this warp produces
    const int rbw  = bt * (4 * MPW) + wr * MPW;
    const int fbase = bt * 64 + wr * 2;
    const int fown  = fbase + c * 8 + wc;
    // flag this lane checks during the group wait (lanes 0..15)
    const int fpoll = fbase + (L >> 1) * 8 + (L & 1);

    float hold[MPW * 8];
#pragma unroll
    for (int i = 0; i < MPW * 8; i++) hold[i] = 0.0f;
    uint4 own_fa[MPW];
#pragma unroll
    for (int m = 0; m < MPW; m++) own_fa[m] = make_uint4(0u, 0u, 0u, 0u);

    for (int t = 0; t < Wlen; t++) {
        const int par = t & 1;
        const unsigned thr = 32u * (unsigned)t;
        float acc[MPW][6][4];
#pragma unroll
        for (int m = 0; m < MPW; m++)
#pragma unroll
            for (int nf = 0; nf < 6; nf++)
#pragma unroll
                for (int u = 0; u < 4; u++) acc[m][nf][u] = 0.0f;

        // build x-fold A fragment (x regs die here; reloaded in epilogue)
        uint4 xfrag[MPW];
#pragma unroll
        for (int m = 0; m < MPW; m++) {
            const int row0 = (rbw + m) * 16 + (L >> 2);
            const float4* xp0 = (const float4*)(x + (size_t)row0 * (Wlen * Fin) + t * Fin);
            const float4* xp1 = (const float4*)(x + (size_t)(row0 + 8) * (Wlen * Fin) + t * Fin);
            float4 a0 = __ldg(xp0), a1 = __ldg(xp0 + 1);
            float4 b0 = __ldg(xp1), b1 = __ldg(xp1 + 1);
            const float f0[8] = {a0.x, a0.y, a0.z, a0.w, a1.x, a1.y, a1.z, a1.w};
            const float f1[8] = {b0.x, b0.y, b0.z, b0.w, b1.x, b1.y, b1.z, b1.w};
            const int c0 = (L & 3) << 1;
            const unsigned one = ((L & 3) == 0) ? f2h2(1.0f, 0.0f) : 0u;
            xfrag[m].x = f2h2(f0[c0], f0[c0 + 1]);
            xfrag[m].y = f2h2(f1[c0], f1[c0 + 1]);
            xfrag[m].z = one;
            xfrag[m].w = one;
        }

        const unsigned* Ah = g_hA + ((size_t)par * 128 + rbw) * 2048;

        // ---- ONE group wait: 16 producer flags checked by 16 lanes --------
        {
            unsigned rdy = 1u;
            if (L < 16) rdy = (ld_acq(&g_flag[fpoll]) >= thr) ? 1u : 0u;
            long guard = 0;
            while (__ballot_sync(0xffffffffu, rdy) != 0xffffffffu &&
                   guard < 200000000L) {
                if (L < 16 && !rdy)
                    rdy = (ld_acq(&g_flag[fpoll]) >= thr) ? 1u : 0u;
                guard++;
            }
        }

        // ---- issue ALL 15 foreign A loads back-to-back (MLP=15) -----------
        uint4 F1[8][MPW], F2[7][MPW];
#pragma unroll
        for (int d = 0; d < 8; d++) {
            const int qn = (qw + 1 + d) & 15;
#pragma unroll
            for (int m = 0; m < MPW; m++)
                F1[d][m] = __ldcg((const uint4*)(Ah + (size_t)m * 2048 + qn * 128) + L);
        }
#pragma unroll
        for (int d = 0; d < 7; d++) {
            const int qn = (qw + 9 + d) & 15;
#pragma unroll
            for (int m = 0; m < MPW; m++)
                F2[d][m] = __ldcg((const uint4*)(Ah + (size_t)m * 2048 + qn * 128) + L);
        }

        // ---- MMAs: own + xfold first (registers), then foreign in order ---
        MMA_CHUNK(qw, own_fa);
        MMA_CHUNK(16, xfrag);
#pragma unroll
        for (int d = 0; d < 8; d++) MMA_CHUNK((qw + 1 + d) & 15, F1[d]);
#pragma unroll
        for (int d = 0; d < 7; d++) MMA_CHUNK((qw + 9 + d) & 15, F2[d]);

        // ---- epilogue: inn (x-only, fp32) + gates + h update + store ------
        const int pw = par ^ 1;
#pragma unroll
        for (int m = 0; m < MPW; m++) {
            const int rb = rbw + m;
            unsigned whi[4];
#pragma unroll
            for (int rh = 0; rh < 2; rh++) {
                const int row = (rbw + m) * 16 + (L >> 2) + 8 * rh;
                const float4* xp = (const float4*)(x + (size_t)row * (Wlen * Fin) + t * Fin);
                float4 e0 = __ldg(xp), e1 = __ldg(xp + 1);
                const float x8[8] = {e0.x, e0.y, e0.z, e0.w, e1.x, e1.y, e1.z, e1.w};
#pragma unroll
                for (int fp = 0; fp < 2; fp++) {
                    float hpair[2];
#pragma unroll
                    for (int e = 0; e < 2; e++) {
                        const int jl = wc * 16 + 2 * (L & 3) + 8 * fp + e;
                        const int j  = c * 32 + jl;
                        const float* wj = swxn + jl * 8;
                        float xn = sbin[j];
#pragma unroll
                        for (int u = 0; u < 8; u++) xn = fmaf(x8[u], wj[u], xn);
                        const int ci = rh * 2 + e;
                        float rp  = acc[m][fp][ci];          // bias+x folded
                        float zp  = acc[m][2 + fp][ci];
                        float hnv = acc[m][4 + fp][ci];      // includes bhn
                        float r = __fdividef(1.0f, 1.0f + __expf(-rp));
                        float z = __fdividef(1.0f, 1.0f + __expf(-zp));
                        float an = xn + r * hnv;
                        an = fminf(fmaxf(an, -15.0f), 15.0f);
                        float e2 = __expf(-2.0f * an);
                        float n  = (1.0f - e2) * __fdividef(1.0f, 1.0f + e2);
                        const int hidx = ((m * 2 + rh) * 2 + fp) * 2 + e;
                        float h = (1.0f - z) * n + z * hold[hidx];
                        hold[hidx] = h;
                        hpair[e] = h;
                    }
                    whi[rh + 2 * fp] = f2h2(hpair[0], hpair[1]);
                }
            }
            own_fa[m] = make_uint4(whi[0], whi[1], whi[2], whi[3]);
            *(((uint4*)(g_hA + ((size_t)pw * 128 + rb) * 2048 + qw * 128)) + L) = own_fa[m];
        }
        red_rel_add(&g_flag[fown], 1u);
    }

    // final h -> plain layout
#pragma unroll
    for (int m = 0; m < MPW; m++)
#pragma unroll
        for (int rh = 0; rh < 2; rh++) {
            const int row = (rbw + m) * 16 + (L >> 2) + 8 * rh;
#pragma unroll
            for (int fp = 0; fp < 2; fp++)
#pragma unroll
                for (int e = 0; e < 2; e++) {
                    const int jl = wc * 16 + 2 * (L & 3) + 8 * fp + e;
                    const int hidx = ((m * 2 + rh) * 2 + fp) * 2 + e;
                    g_hfinal[(size_t)row * 256 + c * 32 + jl] = hold[hidx];
                }
        }
}

// ---------------- head: h_bwd + projection + GELU + LayerNorm ---------------
__global__ void __launch_bounds__(256)
head_kernel(const float* __restrict__ x,
            const float* __restrict__ Wih_b,
            const float* __restrict__ bih_b,
            const float* __restrict__ bhh_b,
            const float* __restrict__ bp,
            const float* __restrict__ gamma,
            const float* __restrict__ beta,
            float* __restrict__ out) {
    __shared__ float hf[8][Hdim];
    __shared__ float hb[8][Hdim];
    __shared__ float ys[8][Hdim];
    __shared__ float xs[8][Fin];

    const int tx = threadIdx.x;
    const int b0 = blockIdx.x * 8;

    for (int idx = tx; idx < 8 * Hdim; idx += 256) {
        int r = idx >> 8, k = idx & 255;
        hf[r][k] = g_hfinal[(size_t)(b0 + r) * Hdim + k];
    }
    if (tx < 64) {
        int r = tx >> 3, cc = tx & 7;
        xs[r][cc] = x[(size_t)(b0 + r) * (Wlen * Fin) + (Wlen - 1) * Fin + cc];
    }
    __syncthreads();

    {   // backward cell at h0 = 0
        const int j = tx;
        float wr[Fin], wz[Fin], wn[Fin];
#pragma unroll
        for (int cc = 0; cc < Fin; cc++) {
            wr[cc] = Wih_b[j * Fin + cc];
            wz[cc] = Wih_b[(256 + j) * Fin + cc];
            wn[cc] = Wih_b[(512 + j) * Fin + cc];
        }
        const float bir = bih_b[j],       bhr = bhh_b[j];
        const float biz = bih_b[256 + j], bhz = bhh_b[256 + j];
        const float bin = bih_b[512 + j], bhn = bhh_b[512 + j];
#pragma unroll
        for (int r8 = 0; r8 < 8; r8++) {
            float gr = bir + bhr, gz = biz + bhz, gn = bin;
#pragma unroll
            for (int cc = 0; cc < Fin; cc++) {
                float xvv = xs[r8][cc];
                gr = fmaf(xvv, wr[cc], gr);
                gz = fmaf(xvv, wz[cc], gz);
                gn = fmaf(xvv, wn[cc], gn);
            }
            float r = 1.0f / (1.0f + __expf(-gr));
            float z = 1.0f / (1.0f + __expf(-gz));
            float an = gn + r * bhn;
            an = fminf(fmaxf(an, -15.0f), 15.0f);
            float e = __expf(-2.0f * an);
            float n = (1.0f - e) / (1.0f + e);
            hb[r8][j] = (1.0f - z) * n;
        }
    }
    __syncthreads();

    {   // projection + exact GELU
        const int j = tx;
#pragma unroll
        for (int r8 = 0; r8 < 8; r8++) {
            float acc = bp[j];
#pragma unroll 4
            for (int k = 0; k < Hdim; k++)
                acc = fmaf(hf[r8][k], g_Wpt[k * Hdim + j], acc);
#pragma unroll 4
            for (int k = 0; k < Hdim; k++)
                acc = fmaf(hb[r8][k], g_Wpt[(Hdim + k) * Hdim + j], acc);
            ys[r8][j] = 0.5f * acc * (1.0f + erff(acc * 0.70710678118654752f));
        }
    }
    __syncthreads();

    const int w = tx >> 5, l = tx & 31;
    float s1 = 0.f, s2 = 0.f;
#pragma unroll
    for (int m = 0; m < 8; m++) {
        float v = ys[w][l + 32 * m];
        s1 += v; s2 += v * v;
    }
#pragma unroll
    for (int o = 16; o > 0; o >>= 1) {
        s1 += __shfl_xor_sync(0xffffffffu, s1, o);
        s2 += __shfl_xor_sync(0xffffffffu, s2, o);
    }
    const float mu  = s1 * (1.0f / 256.0f);
    const float var = s2 * (1.0f / 256.0f) - mu * mu;
    const float inv = rsqrtf(var + 1e-5f);
#pragma unroll
    for (int m = 0; m < 8; m++) {
        int col = l + 32 * m;
        float v = (ys[w][col] - mu) * inv;
        out[(size_t)(b0 + w) * Hdim + col] = v * gamma[col] + beta[col];
    }
}

// ---------------------------------------------------------------------------
extern "C" void kernel_launch(void* const* d_in, const int* in_sizes, int n_in,
                              void* d_out, int out_size) {
    const float* x     = (const float*)d_in[0];
    const float* Wih_f = (const float*)d_in[1];
    const float* Whh_f = (const float*)d_in[2];
    const float* bih_f = (const float*)d_in[3];
    const float* bhh_f = (const float*)d_in[4];
    const float* Wih_b = (const float*)d_in[5];
    /* Whh_b = d_in[6] unused: backward cell has h0 = 0 */
    const float* bih_b = (const float*)d_in[7];
    const float* bhh_b = (const float*)d_in[8];
    const float* Wp    = (const float*)d_in[9];
    const float* bp    = (const float*)d_in[10];
    const float* gamma = (const float*)d_in[11];
    const float* beta  = (const float*)d_in[12];
    float* out = (float*)d_out;

    cudaFuncSetAttribute(gru_persist<1>, cudaFuncAttributeMaxDynamicSharedMemorySize, SM_TOTAL);
    cudaFuncSetAttribute(gru_persist<2>, cudaFuncAttributeMaxDynamicSharedMemorySize, SM_TOTAL);

    int dev = 0, sms = 0, nb = 0;
    cudaGetDevice(&dev);
    cudaDeviceGetAttribute(&sms, cudaDevAttrMultiProcessorCount, dev);
    cudaOccupancyMaxActiveBlocksPerMultiprocessor(&nb, gru_persist<1>, 256, SM_TOTAL);

    prep_kernel<<<(N_PREP + 255) / 256, 256>>>(Whh_f, Wih_f, bih_f, bhh_f, Wp);

    if ((long)nb * sms >= 256)
        gru_persist<1><<<256, 256, SM_TOTAL>>>(x);
    else
        gru_persist<2><<<128, 256, SM_TOTAL>>>(x);

    head_kernel<<<Bsz / 8, 256>>>(x, Wih_b, bih_b, bhh_b, bp, gamma, beta, out);
}

// round 10
// speedup vs baseline: 1.5207x; 1.0974x over previous
#include <cuda_runtime.h>
#include <cuda_bf16.h>
#include <cuda_fp16.h>
#include <math.h>

// StatEncoder — persistent mma.sync fp16 GRU, plain sm_100 target.
//   Single-pass fp16 (R8/R9 math, rel_err 5e-5): D = A[M,272] @ W^T,
//   17 K-chunks (16 h + x-fold with biases at k8). inn gate fp32 SIMT.
//   R10: register-budgeted schedule. Own+xfold MMAs fire BEFORE the single
//   group wait; foreign chunks flow through a depth-8 register ring
//   (consume slot, reissue load into it) with no waits inside the ring.

#define Bsz   2048
#define Wlen  128
#define Fin   8
#define Hdim  256

#define N_WF   104448          // 8c x 17q x 12nf x 64 words
#define N_WXN  2048            // 8c x 32jl x 8 (Wih_n for inn)
#define N_BIN  256
#define N_HZ0  262144          // parity-0 A plane words
#define N_WPT  131072
#define NFLAG  2048

// dynamic smem layout (bytes)
#define SM_WXN    52224
#define SM_BIN    53248
#define SM_TOTAL  54272

// ---- static device scratch ----
__device__ __align__(256) unsigned g_wfrag[N_WF];
__device__ __align__(256) float    g_wxn[N_WXN];
__device__ __align__(256) float    g_bin[N_BIN];
// [par][rb(128)][q(16)][128 words]  (single fp16 plane)
__device__ __align__(256) unsigned g_hA[2 * 128 * 16 * 128];
__device__ __align__(256) float    g_hfinal[Bsz * Hdim];
__device__ __align__(256) float    g_Wpt[N_WPT];
__device__ int g_flag[NFLAG];

// ---- helpers ----
static __device__ __forceinline__ unsigned f2h2(float a, float b) {
    return (unsigned)__half_as_ushort(__float2half_rn(a)) |
           ((unsigned)__half_as_ushort(__float2half_rn(b)) << 16);
}
static __device__ __forceinline__ unsigned ld_acq(const int* p) {
    unsigned v;
    asm volatile("ld.acquire.gpu.global.u32 %0, [%1];" : "=r"(v) : "l"(p) : "memory");
    return v;
}
static __device__ __forceinline__ void red_rel_add(int* p, unsigned v) {
    asm volatile("red.release.gpu.global.add.u32 [%0], %1;" :: "l"(p), "r"(v) : "memory");
}

#define MMAH(d, a, b0v, b1v)                                                   \
    asm volatile(                                                              \
        "mma.sync.aligned.m16n8k16.row.col.f32.f16.f16.f32 "                   \
        "{%0,%1,%2,%3}, {%4,%5,%6,%7}, {%8,%9}, {%0,%1,%2,%3};"                \
        : "+f"(d[0]), "+f"(d[1]), "+f"(d[2]), "+f"(d[3])                       \
        : "r"(a.x), "r"(a.y), "r"(a.z), "r"(a.w), "r"(b0v), "r"(b1v))

// one K-chunk = 6 MMAs against SMEM-resident B fragments
#define MMA_CHUNK(qidx, afr)                                                   \
    {                                                                          \
        const int bb_ = ((qidx) * 12 + wc * 6) * 64 + (L << 1);                \
        _Pragma("unroll")                                                      \
        for (int nf_ = 0; nf_ < 6; nf_++) {                                    \
            uint2 bw_ = *(const uint2*)(Wf + bb_ + nf_ * 64);                  \
            _Pragma("unroll")                                                  \
            for (int m_ = 0; m_ < MPW; m_++)                                   \
                MMAH(acc[m_][nf_], (afr)[m_], bw_.x, bw_.y);                   \
        }                                                                      \
    }

// ---------------- prep ------------------------------------------------------
#define N_PREP (N_WF + N_WXN + N_BIN + N_HZ0 + NFLAG + N_WPT)

__global__ void prep_kernel(const float* __restrict__ Whh_f,
                            const float* __restrict__ Wih_f,
                            const float* __restrict__ bih_f,
                            const float* __restrict__ bhh_f,
                            const float* __restrict__ Wp) {
    int idx = blockIdx.x * blockDim.x + threadIdx.x;
    if (idx < N_WF) {
        int c  = idx / 13056, r = idx % 13056;
        int q  = r / 768,     r3 = r % 768;
        int nfg = r3 / 64,    r4 = r3 % 64;
        int L  = r4 >> 1,     ws = r4 & 1;
        int n  = nfg * 8 + (L >> 2);
        int wc = n / 48, r5 = n % 48;
        int gate = r5 / 16;                 // 0=r, 1=z, 2=hn
        int jl = wc * 16 + (r5 % 16);
        int j  = c * 32 + jl;
        float v0, v1;
        if (q < 16) {
            int k0 = q * 16 + ((L & 3) << 1) + ws * 8;
            v0 = Whh_f[(gate * 256 + j) * 256 + k0];
            v1 = Whh_f[(gate * 256 + j) * 256 + k0 + 1];
        } else {
            int kb = ((L & 3) << 1) + ws * 8;
            float e[2];
#pragma unroll
            for (int u = 0; u < 2; u++) {
                int kk = kb + u;
                float v = 0.0f;
                if (kk < 8) {
                    if (gate < 2) v = Wih_f[(gate * 256 + j) * 8 + kk];
                } else if (kk == 8) {
                    if (gate == 0)      v = bih_f[j] + bhh_f[j];
                    else if (gate == 1) v = bih_f[256 + j] + bhh_f[256 + j];
                    else                v = bhh_f[512 + j];
                }
                e[u] = v;
            }
            v0 = e[0]; v1 = e[1];
        }
        g_wfrag[idx] = f2h2(v0, v1);
    } else if (idx < N_WF + N_WXN) {
        int i = idx - N_WF;
        int c = i / 256, r = i % 256;
        int jl = r / 8, e = r % 8;
        int j = c * 32 + jl;
        g_wxn[i] = Wih_f[(512 + j) * 8 + e];
    } else if (idx < N_WF + N_WXN + N_BIN) {
        int j = idx - N_WF - N_WXN;
        g_bin[j] = bih_f[512 + j];
    } else if (idx < N_WF + N_WXN + N_BIN + N_HZ0) {
        g_hA[idx - N_WF - N_WXN - N_BIN] = 0u;     // parity-0 plane = h(0) = 0
    } else if (idx < N_WF + N_WXN + N_BIN + N_HZ0 + NFLAG) {
        g_flag[idx - N_WF - N_WXN - N_BIN - N_HZ0] = 0;
    } else if (idx < N_PREP) {
        int i = idx - N_WF - N_WXN - N_BIN - N_HZ0 - NFLAG;
        int m = i / Hdim, j = i - m * Hdim;
        g_Wpt[i] = Wp[j * (2 * Hdim) + m];
    }
}

// ---------------- persistent GRU -------------------------------------------
template<int MPW>
__global__ void __launch_bounds__(256, 2)
gru_persist(const float* __restrict__ x) {
    extern __shared__ unsigned smem[];
    const int tid = threadIdx.x;
    const int bt = blockIdx.x >> 3;     // batch-tile group
    const int c  = blockIdx.x & 7;      // column group 0..7
    constexpr int RD = 8 / MPW;         // foreign-fragment ring depth

    // resident weights
    {
        const uint4* src = (const uint4*)(g_wfrag + c * 13056);
        uint4* dst = (uint4*)smem;
        for (int i = tid; i < 3264; i += 256) dst[i] = src[i];
        float* wxd = (float*)((char*)smem + SM_WXN);
        const float* wxs = g_wxn + c * 256;
        for (int i = tid; i < 256; i += 256) wxd[i] = wxs[i];
        float* bd = (float*)((char*)smem + SM_BIN);
        for (int i = tid; i < 256; i += 256) bd[i] = g_bin[i];
    }
    __syncthreads();

    const int w  = tid >> 5, L = tid & 31;
    const int wr = w >> 1;              // warp row-group
    const int wc = w & 1;               // N col half (16 jl)
    const unsigned* Wf = smem;          // fp16 B frags, 17 chunks
    const float* swxn = (const float*)((char*)smem + SM_WXN);
    const float* sbin = (const float*)((char*)smem + SM_BIN);
    const int qw   = 2 * c + wc;        // K-chunk this warp produces
    const int rbw  = bt * (4 * MPW) + wr * MPW;
    const int fbase = bt * 64 + wr * 2;
    const int fown  = fbase + c * 8 + wc;
    const int fpoll = fbase + (L >> 1) * 8 + (L & 1);  // lanes 0..15

    float hold[MPW * 8];
#pragma unroll
    for (int i = 0; i < MPW * 8; i++) hold[i] = 0.0f;
    uint4 own_fa[MPW];
#pragma unroll
    for (int m = 0; m < MPW; m++) own_fa[m] = make_uint4(0u, 0u, 0u, 0u);

    for (int t = 0; t < Wlen; t++) {
        const int par = t & 1;
        const unsigned thr = 32u * (unsigned)t;
        float acc[MPW][6][4];
#pragma unroll
        for (int m = 0; m < MPW; m++)
#pragma unroll
            for (int nf = 0; nf < 6; nf++)
#pragma unroll
                for (int u = 0; u < 4; u++) acc[m][nf][u] = 0.0f;

        // x(t) load (kept live through the epilogue) + x-fold A fragment
        float4 xv[MPW * 2][2];
        uint4 xfrag[MPW];
#pragma unroll
        for (int m = 0; m < MPW; m++) {
#pragma unroll
            for (int rh = 0; rh < 2; rh++) {
                const int row = (rbw + m) * 16 + (L >> 2) + 8 * rh;
                const float4* xp = (const float4*)(x + (size_t)row * (Wlen * Fin) + t * Fin);
                xv[m * 2 + rh][0] = __ldg(xp);
                xv[m * 2 + rh][1] = __ldg(xp + 1);
            }
            const float* f0 = (const float*)&xv[m * 2 + 0][0];
            const float* f1 = (const float*)&xv[m * 2 + 1][0];
            const int c0 = (L & 3) << 1;
            const unsigned one = ((L & 3) == 0) ? f2h2(1.0f, 0.0f) : 0u;
            xfrag[m].x = f2h2(f0[c0], f0[c0 + 1]);
            xfrag[m].y = f2h2(f1[c0], f1[c0 + 1]);
            xfrag[m].z = one;
            xfrag[m].w = one;
        }

        // own + x-fold MMAs: register/SMEM-only, overlap the group wait below
        MMA_CHUNK(qw, own_fa);
        MMA_CHUNK(16, xfrag);

        // ---- ONE group wait: 16 producer flags checked by 16 lanes --------
        {
            unsigned rdy = 1u;
            if (L < 16) rdy = (ld_acq(&g_flag[fpoll]) >= thr) ? 1u : 0u;
            long guard = 0;
            while (__ballot_sync(0xffffffffu, rdy) != 0xffffffffu &&
                   guard < 200000000L) {
                if (L < 16 && !rdy)
                    rdy = (ld_acq(&g_flag[fpoll]) >= thr) ? 1u : 0u;
                guard++;
            }
        }

        const unsigned* Ah = g_hA + ((size_t)par * 128 + rbw) * 2048;

        // ---- depth-RD register ring over the 15 foreign chunks ------------
        uint4 F[RD][MPW];
#pragma unroll
        for (int d = 0; d < RD; d++) {
            const int qn = (qw + 1 + d) & 15;
#pragma unroll
            for (int m = 0; m < MPW; m++)
                F[d][m] = __ldcg((const uint4*)(Ah + (size_t)m * 2048 + qn * 128) + L);
        }
#pragma unroll
        for (int d = 0; d < 15; d++) {
            const int s = d % RD;
            MMA_CHUNK((qw + 1 + d) & 15, F[s]);
            if (d + RD < 15) {
                const int qn = (qw + 1 + d + RD) & 15;
#pragma unroll
                for (int m = 0; m < MPW; m++)
                    F[s][m] = __ldcg((const uint4*)(Ah + (size_t)m * 2048 + qn * 128) + L);
            }
        }

        // ---- epilogue: inn (x-only, fp32) + gates + h update + store ------
        const int pw = par ^ 1;
#pragma unroll
        for (int m = 0; m < MPW; m++) {
            const int rb = rbw + m;
            unsigned whi[4];
#pragma unroll
            for (int rh = 0; rh < 2; rh++) {
                const float* x8 = (const float*)&xv[m * 2 + rh][0];
#pragma unroll
                for (int fp = 0; fp < 2; fp++) {
                    float hpair[2];
#pragma unroll
                    for (int e = 0; e < 2; e++) {
                        const int jl = wc * 16 + 2 * (L & 3) + 8 * fp + e;
                        const int j  = c * 32 + jl;
                        const float* wj = swxn + jl * 8;
                        float xn = sbin[j];
#pragma unroll
                        for (int u = 0; u < 8; u++) xn = fmaf(x8[u], wj[u], xn);
                        const int ci = rh * 2 + e;
                        float rp  = acc[m][fp][ci];          // bias+x folded
                        float zp  = acc[m][2 + fp][ci];
                        float hnv = acc[m][4 + fp][ci];      // includes bhn
                        float r = __fdividef(1.0f, 1.0f + __expf(-rp));
                        float z = __fdividef(1.0f, 1.0f + __expf(-zp));
                        float an = xn + r * hnv;
                        an = fminf(fmaxf(an, -15.0f), 15.0f);
                        float e2 = __expf(-2.0f * an);
                        float n  = (1.0f - e2) * __fdividef(1.0f, 1.0f + e2);
                        const int hidx = ((m * 2 + rh) * 2 + fp) * 2 + e;
                        float h = (1.0f - z) * n + z * hold[hidx];
                        hold[hidx] = h;
                        hpair[e] = h;
                    }
                    whi[rh + 2 * fp] = f2h2(hpair[0], hpair[1]);
                }
            }
            own_fa[m] = make_uint4(whi[0], whi[1], whi[2], whi[3]);
            *(((uint4*)(g_hA + ((size_t)pw * 128 + rb) * 2048 + qw * 128)) + L) = own_fa[m];
        }
        red_rel_add(&g_flag[fown], 1u);
    }

    // final h -> plain layout
#pragma unroll
    for (int m = 0; m < MPW; m++)
#pragma unroll
        for (int rh = 0; rh < 2; rh++) {
            const int row = (rbw + m) * 16 + (L >> 2) + 8 * rh;
#pragma unroll
            for (int fp = 0; fp < 2; fp++)
#pragma unroll
                for (int e = 0; e < 2; e++) {
                    const int jl = wc * 16 + 2 * (L & 3) + 8 * fp + e;
                    const int hidx = ((m * 2 + rh) * 2 + fp) * 2 + e;
                    g_hfinal[(size_t)row * 256 + c * 32 + jl] = hold[hidx];
                }
        }
}

// ---------------- head: h_bwd + projection + GELU + LayerNorm ---------------
__global__ void __launch_bounds__(256)
head_kernel(const float* __restrict__ x,
            const float* __restrict__ Wih_b,
            const float* __restrict__ bih_b,
            const float* __restrict__ bhh_b,
            const float* __restrict__ bp,
            const float* __restrict__ gamma,
            const float* __restrict__ beta,
            float* __restrict__ out) {
    __shared__ float hf[8][Hdim];
    __shared__ float hb[8][Hdim];
    __shared__ float ys[8][Hdim];
    __shared__ float xs[8][Fin];

    const int tx = threadIdx.x;
    const int b0 = blockIdx.x * 8;

    for (int idx = tx; idx < 8 * Hdim; idx += 256) {
        int r = idx >> 8, k = idx & 255;
        hf[r][k] = g_hfinal[(size_t)(b0 + r) * Hdim + k];
    }
    if (tx < 64) {
        int r = tx >> 3, cc = tx & 7;
        xs[r][cc] = x[(size_t)(b0 + r) * (Wlen * Fin) + (Wlen - 1) * Fin + cc];
    }
    __syncthreads();

    {   // backward cell at h0 = 0
        const int j = tx;
        float wr[Fin], wz[Fin], wn[Fin];
#pragma unroll
        for (int cc = 0; cc < Fin; cc++) {
            wr[cc] = Wih_b[j * Fin + cc];
            wz[cc] = Wih_b[(256 + j) * Fin + cc];
            wn[cc] = Wih_b[(512 + j) * Fin + cc];
        }
        const float bir = bih_b[j],       bhr = bhh_b[j];
        const float biz = bih_b[256 + j], bhz = bhh_b[256 + j];
        const float bin = bih_b[512 + j], bhn = bhh_b[512 + j];
#pragma unroll
        for (int r8 = 0; r8 < 8; r8++) {
            float gr = bir + bhr, gz = biz + bhz, gn = bin;
#pragma unroll
            for (int cc = 0; cc < Fin; cc++) {
                float xvv = xs[r8][cc];
                gr = fmaf(xvv, wr[cc], gr);
                gz = fmaf(xvv, wz[cc], gz);
                gn = fmaf(xvv, wn[cc], gn);
            }
            float r = 1.0f / (1.0f + __expf(-gr));
            float z = 1.0f / (1.0f + __expf(-gz));
            float an = gn + r * bhn;
            an = fminf(fmaxf(an, -15.0f), 15.0f);
            float e = __expf(-2.0f * an);
            float n = (1.0f - e) / (1.0f + e);
            hb[r8][j] = (1.0f - z) * n;
        }
    }
    __syncthreads();

    {   // projection + exact GELU
        const int j = tx;
#pragma unroll
        for (int r8 = 0; r8 < 8; r8++) {
            float acc = bp[j];
#pragma unroll 4
            for (int k = 0; k < Hdim; k++)
                acc = fmaf(hf[r8][k], g_Wpt[k * Hdim + j], acc);
#pragma unroll 4
            for (int k = 0; k < Hdim; k++)
                acc = fmaf(hb[r8][k], g_Wpt[(Hdim + k) * Hdim + j], acc);
            ys[r8][j] = 0.5f * acc * (1.0f + erff(acc * 0.70710678118654752f));
        }
    }
    __syncthreads();

    const int w = tx >> 5, l = tx & 31;
    float s1 = 0.f, s2 = 0.f;
#pragma unroll
    for (int m = 0; m < 8; m++) {
        float v = ys[w][l + 32 * m];
        s1 += v; s2 += v * v;
    }
#pragma unroll
    for (int o = 16; o > 0; o >>= 1) {
        s1 += __shfl_xor_sync(0xffffffffu, s1, o);
        s2 += __shfl_xor_sync(0xffffffffu, s2, o);
    }
    const float mu  = s1 * (1.0f / 256.0f);
    const float var = s2 * (1.0f / 256.0f) - mu * mu;
    const float inv = rsqrtf(var + 1e-5f);
#pragma unroll
    for (int m = 0; m < 8; m++) {
        int col = l + 32 * m;
        float v = (ys[w][col] - mu) * inv;
        out[(size_t)(b0 + w) * Hdim + col] = v * gamma[col] + beta[col];
    }
}

// ---------------------------------------------------------------------------
extern "C" void kernel_launch(void* const* d_in, const int* in_sizes, int n_in,
                              void* d_out, int out_size) {
    const float* x     = (const float*)d_in[0];
    const float* Wih_f = (const float*)d_in[1];
    const float* Whh_f = (const float*)d_in[2];
    const float* bih_f = (const float*)d_in[3];
    const float* bhh_f = (const float*)d_in[4];
    const float* Wih_b = (const float*)d_in[5];
    /* Whh_b = d_in[6] unused: backward cell has h0 = 0 */
    const float* bih_b = (const float*)d_in[7];
    const float* bhh_b = (const float*)d_in[8];
    const float* Wp    = (const float*)d_in[9];
    const float* bp    = (const float*)d_in[10];
    const float* gamma = (const float*)d_in[11];
    const float* beta  = (const float*)d_in[12];
    float* out = (float*)d_out;

    cudaFuncSetAttribute(gru_persist<1>, cudaFuncAttributeMaxDynamicSharedMemorySize, SM_TOTAL);
    cudaFuncSetAttribute(gru_persist<2>, cudaFuncAttributeMaxDynamicSharedMemorySize, SM_TOTAL);

    int dev = 0, sms = 0, nb = 0;
    cudaGetDevice(&dev);
    cudaDeviceGetAttribute(&sms, cudaDevAttrMultiProcessorCount, dev);
    cudaOccupancyMaxActiveBlocksPerMultiprocessor(&nb, gru_persist<1>, 256, SM_TOTAL);

    prep_kernel<<<(N_PREP + 255) / 256, 256>>>(Whh_f, Wih_f, bih_f, bhh_f, Wp);

    if ((long)nb * sms >= 256)
        gru_persist<1><<<256, 256, SM_TOTAL>>>(x);
    else
        gru_persist<2><<<128, 256, SM_TOTAL>>>(x);

    head_kernel<<<Bsz / 8, 256>>>(x, Wih_b, bih_b, bhh_b, bp, gamma, beta, out);
}

// round 11
// speedup vs baseline: 2.5065x; 1.6483x over previous
#include <cuda_runtime.h>
#include <cuda_bf16.h>
#include <cuda_fp16.h>
#include <math.h>

// StatEncoder — persistent mma.sync fp16 GRU, plain sm_100 target.
//   R11: ZERO inter-CTA communication. 128 CTAs x 512 threads; each CTA owns
//   M=16 batch rows and ALL 768 gate columns. h lives in SMEM (fp16 A-frag
//   layout, parity double-buffered); warps exchange via ONE __syncthreads per
//   step. Weights: 8 of 17 K-chunks SMEM-resident (incl x-fold), 9 streamed
//   from L2 (shared by all CTAs -> L2-hot) through a depth-3 register ring.
//   Math identical to R8-R10 (single-pass fp16, fp32 state, rel_err ~5e-5).

#define Bsz   2048
#define Wlen  128
#define Fin   8
#define Hdim  256
#define THREADS 512

#define N_WF   104448          // 8c x 17q x 12nf x 64 words
#define N_WXN  2048            // 8c x 32jl x 8 (Wih_n for inn)
#define N_BIN  256
#define N_WPT  131072

// dynamic smem layout (32-bit words)
#define SW_RES 0               // resident B frags: [c(8)][slot(8)][768]
#define SW_H   49152           // h A-buffer: [par(2)][chunk(16)][128]
#define SW_WXN 53248           // 2048 floats
#define SW_BIN 55296           // 256 floats
#define SM_WORDS 55552
#define SM_TOTAL (SM_WORDS * 4)   // 222,208 B

// ---- static device scratch ----
__device__ __align__(256) unsigned g_wfrag[N_WF];
__device__ __align__(256) float    g_wxn[N_WXN];
__device__ __align__(256) float    g_bin[N_BIN];
__device__ __align__(256) float    g_hfinal[Bsz * Hdim];
__device__ __align__(256) float    g_Wpt[N_WPT];

// ---- helpers ----
static __device__ __forceinline__ unsigned f2h2(float a, float b) {
    return (unsigned)__half_as_ushort(__float2half_rn(a)) |
           ((unsigned)__half_as_ushort(__float2half_rn(b)) << 16);
}

#define MMAH(d, a, b0v, b1v)                                                   \
    asm volatile(                                                              \
        "mma.sync.aligned.m16n8k16.row.col.f32.f16.f16.f32 "                   \
        "{%0,%1,%2,%3}, {%4,%5,%6,%7}, {%8,%9}, {%0,%1,%2,%3};"                \
        : "+f"(d[0]), "+f"(d[1]), "+f"(d[2]), "+f"(d[3])                       \
        : "r"(a.x), "r"(a.y), "r"(a.z), "r"(a.w), "r"(b0v), "r"(b1v))

// ---------------- prep (g_wfrag / g_wxn / g_bin / g_Wpt; layouts as R10) ----
#define N_PREP (N_WF + N_WXN + N_BIN + N_WPT)

__global__ void prep_kernel(const float* __restrict__ Whh_f,
                            const float* __restrict__ Wih_f,
                            const float* __restrict__ bih_f,
                            const float* __restrict__ bhh_f,
                            const float* __restrict__ Wp) {
    int idx = blockIdx.x * blockDim.x + threadIdx.x;
    if (idx < N_WF) {
        int c  = idx / 13056, r = idx % 13056;
        int q  = r / 768,     r3 = r % 768;
        int nfg = r3 / 64,    r4 = r3 % 64;
        int L  = r4 >> 1,     ws = r4 & 1;
        int n  = nfg * 8 + (L >> 2);
        int wc = n / 48, r5 = n % 48;
        int gate = r5 / 16;                 // 0=r, 1=z, 2=hn
        int jl = wc * 16 + (r5 % 16);
        int j  = c * 32 + jl;
        float v0, v1;
        if (q < 16) {
            int k0 = q * 16 + ((L & 3) << 1) + ws * 8;
            v0 = Whh_f[(gate * 256 + j) * 256 + k0];
            v1 = Whh_f[(gate * 256 + j) * 256 + k0 + 1];
        } else {
            int kb = ((L & 3) << 1) + ws * 8;
            float e[2];
#pragma unroll
            for (int u = 0; u < 2; u++) {
                int kk = kb + u;
                float v = 0.0f;
                if (kk < 8) {
                    if (gate < 2) v = Wih_f[(gate * 256 + j) * 8 + kk];
                } else if (kk == 8) {
                    if (gate == 0)      v = bih_f[j] + bhh_f[j];
                    else if (gate == 1) v = bih_f[256 + j] + bhh_f[256 + j];
                    else                v = bhh_f[512 + j];
                }
                e[u] = v;
            }
            v0 = e[0]; v1 = e[1];
        }
        g_wfrag[idx] = f2h2(v0, v1);
    } else if (idx < N_WF + N_WXN) {
        int i = idx - N_WF;
        int c = i / 256, r = i % 256;
        int jl = r / 8, e = r % 8;
        int j = c * 32 + jl;
        g_wxn[i] = Wih_f[(512 + j) * 8 + e];
    } else if (idx < N_WF + N_WXN + N_BIN) {
        int j = idx - N_WF - N_WXN;
        g_bin[j] = bih_f[512 + j];
    } else if (idx < N_PREP) {
        int i = idx - N_WF - N_WXN - N_BIN;
        int m = i / Hdim, j = i - m * Hdim;
        g_Wpt[i] = Wp[j * (2 * Hdim) + m];
    }
}

// ---------------- persistent GRU (no inter-CTA sync at all) -----------------
__global__ void __launch_bounds__(THREADS, 1)
gru_persist(const float* __restrict__ x) {
    extern __shared__ unsigned smem[];
    const int tid  = threadIdx.x;
    const int bcta = blockIdx.x;        // rows 16*bcta .. 16*bcta+15

    // resident weights: slots 0..6 = chunks 0..6, slot 7 = x-fold chunk 16
    for (int i = tid; i < 49152; i += THREADS) {
        int cc = i / 6144, r = i % 6144;
        int s = r / 768, off = r - s * 768;
        int q = (s < 7) ? s : 16;
        smem[SW_RES + i] = g_wfrag[cc * 13056 + q * 768 + off];
    }
    for (int i = tid; i < 2048; i += THREADS)
        ((float*)(smem + SW_WXN))[i] = g_wxn[i];
    for (int i = tid; i < 256; i += THREADS)
        ((float*)(smem + SW_BIN))[i] = g_bin[i];
    for (int i = tid; i < 2048; i += THREADS)
        smem[SW_H + i] = 0u;            // parity-0 h = h(0) = 0
    __syncthreads();

    const int w  = tid >> 5, L = tid & 31;
    const int c  = w >> 1;              // column group 0..7
    const int wc = w & 1;               // half (16 jl)
    const float* swxn = (const float*)(smem + SW_WXN);
    const float* sbin = (const float*)(smem + SW_BIN);
    const int resbase = c * 6144 + wc * 384;          // + slot*768 + nf*64 + 2L
    const unsigned* gW = g_wfrag + c * 13056 + wc * 384;

    float hold[8];
#pragma unroll
    for (int i = 0; i < 8; i++) hold[i] = 0.0f;

    for (int t = 0; t < Wlen; t++) {
        const int par = t & 1;
        const unsigned* hsrc = smem + SW_H + par * 2048;
        unsigned* hdst = smem + SW_H + (par ^ 1) * 2048;
        __syncthreads();    // h(t) ready; all reads of hdst's old contents done

        float acc[6][4];
#pragma unroll
        for (int nf = 0; nf < 6; nf++)
#pragma unroll
            for (int u = 0; u < 4; u++) acc[nf][u] = 0.0f;

        // x(t) for this lane's two rows + x-fold A fragment
        float x80[8], x81[8];
        uint4 xfrag;
        {
            const int row0 = bcta * 16 + (L >> 2);
            const float4* xp0 = (const float4*)(x + (size_t)row0 * (Wlen * Fin) + t * Fin);
            const float4* xp1 = (const float4*)(x + (size_t)(row0 + 8) * (Wlen * Fin) + t * Fin);
            float4 a0 = __ldg(xp0), a1 = __ldg(xp0 + 1);
            float4 b0 = __ldg(xp1), b1 = __ldg(xp1 + 1);
            x80[0]=a0.x; x80[1]=a0.y; x80[2]=a0.z; x80[3]=a0.w;
            x80[4]=a1.x; x80[5]=a1.y; x80[6]=a1.z; x80[7]=a1.w;
            x81[0]=b0.x; x81[1]=b0.y; x81[2]=b0.z; x81[3]=b0.w;
            x81[4]=b1.x; x81[5]=b1.y; x81[6]=b1.z; x81[7]=b1.w;
            const int c0 = (L & 3) << 1;
            const unsigned one = ((L & 3) == 0) ? f2h2(1.0f, 0.0f) : 0u;
            xfrag.x = f2h2(x80[c0], x80[c0 + 1]);
            xfrag.y = f2h2(x81[c0], x81[c0 + 1]);
            xfrag.z = one;
            xfrag.w = one;
        }

        // prefetch streamed chunks 7,8,9 (read-only, L2-hot, no sync needed)
        uint2 Bs[3][6];
#pragma unroll
        for (int d = 0; d < 3; d++)
#pragma unroll
            for (int nf = 0; nf < 6; nf++)
                Bs[d][nf] = __ldcg((const uint2*)(gW + (7 + d) * 768 + nf * 64 + (L << 1)));

        // x-fold chunk (resident slot 7), A in registers — covers load latency
        {
            const unsigned* bb = smem + resbase + 7 * 768 + (L << 1);
#pragma unroll
            for (int nf = 0; nf < 6; nf++) {
                uint2 bw = *(const uint2*)(bb + nf * 64);
                MMAH(acc[nf], xfrag, bw.x, bw.y);
            }
        }
        // resident h-chunks 0..6 (A from SMEM, B from SMEM)
#pragma unroll
        for (int q = 0; q < 7; q++) {
            uint4 af = *(const uint4*)(hsrc + q * 128 + (L << 2));
            const unsigned* bb = smem + resbase + q * 768 + (L << 1);
#pragma unroll
            for (int nf = 0; nf < 6; nf++) {
                uint2 bw = *(const uint2*)(bb + nf * 64);
                MMAH(acc[nf], af, bw.x, bw.y);
            }
        }
        // streamed h-chunks 7..15 (A from SMEM, B from register ring)
#pragma unroll
        for (int d = 0; d < 9; d++) {
            const int q = 7 + d;
            const int s = d % 3;
            uint4 af = *(const uint4*)(hsrc + q * 128 + (L << 2));
#pragma unroll
            for (int nf = 0; nf < 6; nf++)
                MMAH(acc[nf], af, Bs[s][nf].x, Bs[s][nf].y);
            if (d + 3 < 9) {
#pragma unroll
                for (int nf = 0; nf < 6; nf++)
                    Bs[s][nf] = __ldcg((const uint2*)(gW + (q + 3) * 768 + nf * 64 + (L << 1)));
            }
        }

        // ---- epilogue: inn (x-only, fp32) + gates + h update + STS --------
        unsigned whi[4];
#pragma unroll
        for (int rh = 0; rh < 2; rh++) {
            const float* x8 = rh ? x81 : x80;
#pragma unroll
            for (int fp = 0; fp < 2; fp++) {
                float hpair[2];
#pragma unroll
                for (int e = 0; e < 2; e++) {
                    const int jl = wc * 16 + 2 * (L & 3) + 8 * fp + e;
                    const int j  = c * 32 + jl;
                    const float* wj = swxn + j * 8;
                    float xn = sbin[j];
#pragma unroll
                    for (int u = 0; u < 8; u++) xn = fmaf(x8[u], wj[u], xn);
                    const int ci = rh * 2 + e;
                    float rp  = acc[fp][ci];          // bias+x folded via MMA
                    float zp  = acc[2 + fp][ci];
                    float hnv = acc[4 + fp][ci];      // includes bhn
                    float r = __fdividef(1.0f, 1.0f + __expf(-rp));
                    float z = __fdividef(1.0f, 1.0f + __expf(-zp));
                    float an = xn + r * hnv;
                    an = fminf(fmaxf(an, -15.0f), 15.0f);
                    float e2 = __expf(-2.0f * an);
                    float n  = (1.0f - e2) * __fdividef(1.0f, 1.0f + e2);
                    const int hidx = (rh * 2 + fp) * 2 + e;
                    float h = (1.0f - z) * n + z * hold[hidx];
                    hold[hidx] = h;
                    hpair[e] = h;
                }
                whi[rh + 2 * fp] = f2h2(hpair[0], hpair[1]);
            }
        }
        // warp w produces exactly chunk w (j in [32c+16wc, +16) = 16w..16w+15)
        *(uint4*)(hdst + w * 128 + (L << 2)) =
            make_uint4(whi[0], whi[1], whi[2], whi[3]);
    }

    // final h -> plain layout for the head
#pragma unroll
    for (int rh = 0; rh < 2; rh++) {
        const int row = bcta * 16 + (L >> 2) + 8 * rh;
#pragma unroll
        for (int fp = 0; fp < 2; fp++)
#pragma unroll
            for (int e = 0; e < 2; e++) {
                const int jl = wc * 16 + 2 * (L & 3) + 8 * fp + e;
                const int hidx = (rh * 2 + fp) * 2 + e;
                g_hfinal[(size_t)row * 256 + c * 32 + jl] = hold[hidx];
            }
    }
}

// ---------------- head: h_bwd + projection + GELU + LayerNorm ---------------
__global__ void __launch_bounds__(256)
head_kernel(const float* __restrict__ x,
            const float* __restrict__ Wih_b,
            const float* __restrict__ bih_b,
            const float* __restrict__ bhh_b,
            const float* __restrict__ bp,
            const float* __restrict__ gamma,
            const float* __restrict__ beta,
            float* __restrict__ out) {
    __shared__ float hf[8][Hdim];
    __shared__ float hb[8][Hdim];
    __shared__ float ys[8][Hdim];
    __shared__ float xs[8][Fin];

    const int tx = threadIdx.x;
    const int b0 = blockIdx.x * 8;

    for (int idx = tx; idx < 8 * Hdim; idx += 256) {
        int r = idx >> 8, k = idx & 255;
        hf[r][k] = g_hfinal[(size_t)(b0 + r) * Hdim + k];
    }
    if (tx < 64) {
        int r = tx >> 3, cc = tx & 7;
        xs[r][cc] = x[(size_t)(b0 + r) * (Wlen * Fin) + (Wlen - 1) * Fin + cc];
    }
    __syncthreads();

    {   // backward cell at h0 = 0
        const int j = tx;
        float wr[Fin], wz[Fin], wn[Fin];
#pragma unroll
        for (int cc = 0; cc < Fin; cc++) {
            wr[cc] = Wih_b[j * Fin + cc];
            wz[cc] = Wih_b[(256 + j) * Fin + cc];
            wn[cc] = Wih_b[(512 + j) * Fin + cc];
        }
        const float bir = bih_b[j],       bhr = bhh_b[j];
        const float biz = bih_b[256 + j], bhz = bhh_b[256 + j];
        const float bin = bih_b[512 + j], bhn = bhh_b[512 + j];
#pragma unroll
        for (int r8 = 0; r8 < 8; r8++) {
            float gr = bir + bhr, gz = biz + bhz, gn = bin;
#pragma unroll
            for (int cc = 0; cc < Fin; cc++) {
                float xvv = xs[r8][cc];
                gr = fmaf(xvv, wr[cc], gr);
                gz = fmaf(xvv, wz[cc], gz);
                gn = fmaf(xvv, wn[cc], gn);
            }
            float r = 1.0f / (1.0f + __expf(-gr));
            float z = 1.0f / (1.0f + __expf(-gz));
            float an = gn + r * bhn;
            an = fminf(fmaxf(an, -15.0f), 15.0f);
            float e = __expf(-2.0f * an);
            float n = (1.0f - e) / (1.0f + e);
            hb[r8][j] = (1.0f - z) * n;
        }
    }
    __syncthreads();

    {   // projection + exact GELU
        const int j = tx;
#pragma unroll
        for (int r8 = 0; r8 < 8; r8++) {
            float acc = bp[j];
#pragma unroll 4
            for (int k = 0; k < Hdim; k++)
                acc = fmaf(hf[r8][k], g_Wpt[k * Hdim + j], acc);
#pragma unroll 4
            for (int k = 0; k < Hdim; k++)
                acc = fmaf(hb[r8][k], g_Wpt[(Hdim + k) * Hdim + j], acc);
            ys[r8][j] = 0.5f * acc * (1.0f + erff(acc * 0.70710678118654752f));
        }
    }
    __syncthreads();

    const int w = tx >> 5, l = tx & 31;
    float s1 = 0.f, s2 = 0.f;
#pragma unroll
    for (int m = 0; m < 8; m++) {
        float v = ys[w][l + 32 * m];
        s1 += v; s2 += v * v;
    }
#pragma unroll
    for (int o = 16; o > 0; o >>= 1) {
        s1 += __shfl_xor_sync(0xffffffffu, s1, o);
        s2 += __shfl_xor_sync(0xffffffffu, s2, o);
    }
    const float mu  = s1 * (1.0f / 256.0f);
    const float var = s2 * (1.0f / 256.0f) - mu * mu;
    const float inv = rsqrtf(var + 1e-5f);
#pragma unroll
    for (int m = 0; m < 8; m++) {
        int col = l + 32 * m;
        float v = (ys[w][col] - mu) * inv;
        out[(size_t)(b0 + w) * Hdim + col] = v * gamma[col] + beta[col];
    }
}

// ---------------------------------------------------------------------------
extern "C" void kernel_launch(void* const* d_in, const int* in_sizes, int n_in,
                              void* d_out, int out_size) {
    const float* x     = (const float*)d_in[0];
    const float* Wih_f = (const float*)d_in[1];
    const float* Whh_f = (const float*)d_in[2];
    const float* bih_f = (const float*)d_in[3];
    const float* bhh_f = (const float*)d_in[4];
    const float* Wih_b = (const float*)d_in[5];
    /* Whh_b = d_in[6] unused: backward cell has h0 = 0 */
    const float* bih_b = (const float*)d_in[7];
    const float* bhh_b = (const float*)d_in[8];
    const float* Wp    = (const float*)d_in[9];
    const float* bp    = (const float*)d_in[10];
    const float* gamma = (const float*)d_in[11];
    const float* beta  = (const float*)d_in[12];
    float* out = (float*)d_out;

    cudaFuncSetAttribute(gru_persist, cudaFuncAttributeMaxDynamicSharedMemorySize, SM_TOTAL);

    prep_kernel<<<(N_PREP + 255) / 256, 256>>>(Whh_f, Wih_f, bih_f, bhh_f, Wp);
    gru_persist<<<Bsz / 16, THREADS, SM_TOTAL>>>(x);
    head_kernel<<<Bsz / 8, 256>>>(x, Wih_b, bih_b, bhh_b, bp, gamma, beta, out);
}

// round 12
// speedup vs baseline: 2.5133x; 1.0027x over previous
#include <cuda_runtime.h>
#include <cuda_bf16.h>
#include <cuda_fp16.h>
#include <math.h>

// StatEncoder — persistent mma.sync fp16 GRU, plain sm_100 target.
//   R12 = R11 (zero inter-CTA comm: 128 CTAs x 512 thr, CTA owns 16 rows x
//   all 768 cols, h in SMEM, one __syncthreads/step) + latency fixes:
//   (1) x staged through SMEM, prefetched one step ahead by warp 0
//   (2) streamed-B ring depth 4, all initial loads issued before the
//       x-fold + 7 resident chunks (>=8-chunk prefetch distance)
//   (3) epilogue j-outer: wj loaded once per j (halves epilogue LDS)
//   Math identical to R8-R11 (single-pass fp16, fp32 state).

#define Bsz   2048
#define Wlen  128
#define Fin   8
#define Hdim  256
#define THREADS 512

#define N_WF   104448          // 8c x 17q x 12nf x 64 words
#define N_WXN  2048            // 8c x 32jl x 8 (Wih_n for inn)
#define N_BIN  256
#define N_WPT  131072

// dynamic smem layout (32-bit words)
#define SW_RES 0               // resident B frags: [c(8)][slot(8)][768]
#define SW_H   49152           // h A-buffer: [par(2)][chunk(16)][128]
#define SW_WXN 53248           // 2048 floats
#define SW_BIN 55296           // 256 floats
#define SW_XB  55552           // x stage: [par(2)][row(16)][8] floats
#define SM_WORDS 55808
#define SM_TOTAL (SM_WORDS * 4)   // 223,232 B

// ---- static device scratch ----
__device__ __align__(256) unsigned g_wfrag[N_WF];
__device__ __align__(256) float    g_wxn[N_WXN];
__device__ __align__(256) float    g_bin[N_BIN];
__device__ __align__(256) float    g_hfinal[Bsz * Hdim];
__device__ __align__(256) float    g_Wpt[N_WPT];

// ---- helpers ----
static __device__ __forceinline__ unsigned f2h2(float a, float b) {
    return (unsigned)__half_as_ushort(__float2half_rn(a)) |
           ((unsigned)__half_as_ushort(__float2half_rn(b)) << 16);
}

#define MMAH(d, a, b0v, b1v)                                                   \
    asm volatile(                                                              \
        "mma.sync.aligned.m16n8k16.row.col.f32.f16.f16.f32 "                   \
        "{%0,%1,%2,%3}, {%4,%5,%6,%7}, {%8,%9}, {%0,%1,%2,%3};"                \
        : "+f"(d[0]), "+f"(d[1]), "+f"(d[2]), "+f"(d[3])                       \
        : "r"(a.x), "r"(a.y), "r"(a.z), "r"(a.w), "r"(b0v), "r"(b1v))

// ---------------- prep (identical layouts to R11) ---------------------------
#define N_PREP (N_WF + N_WXN + N_BIN + N_WPT)

__global__ void prep_kernel(const float* __restrict__ Whh_f,
                            const float* __restrict__ Wih_f,
                            const float* __restrict__ bih_f,
                            const float* __restrict__ bhh_f,
                            const float* __restrict__ Wp) {
    int idx = blockIdx.x * blockDim.x + threadIdx.x;
    if (idx < N_WF) {
        int c  = idx / 13056, r = idx % 13056;
        int q  = r / 768,     r3 = r % 768;
        int nfg = r3 / 64,    r4 = r3 % 64;
        int L  = r4 >> 1,     ws = r4 & 1;
        int n  = nfg * 8 + (L >> 2);
        int wc = n / 48, r5 = n % 48;
        int gate = r5 / 16;                 // 0=r, 1=z, 2=hn
        int jl = wc * 16 + (r5 % 16);
        int j  = c * 32 + jl;
        float v0, v1;
        if (q < 16) {
            int k0 = q * 16 + ((L & 3) << 1) + ws * 8;
            v0 = Whh_f[(gate * 256 + j) * 256 + k0];
            v1 = Whh_f[(gate * 256 + j) * 256 + k0 + 1];
        } else {
            int kb = ((L & 3) << 1) + ws * 8;
            float e[2];
#pragma unroll
            for (int u = 0; u < 2; u++) {
                int kk = kb + u;
                float v = 0.0f;
                if (kk < 8) {
                    if (gate < 2) v = Wih_f[(gate * 256 + j) * 8 + kk];
                } else if (kk == 8) {
                    if (gate == 0)      v = bih_f[j] + bhh_f[j];
                    else if (gate == 1) v = bih_f[256 + j] + bhh_f[256 + j];
                    else                v = bhh_f[512 + j];
                }
                e[u] = v;
            }
            v0 = e[0]; v1 = e[1];
        }
        g_wfrag[idx] = f2h2(v0, v1);
    } else if (idx < N_WF + N_WXN) {
        int i = idx - N_WF;
        int c = i / 256, r = i % 256;
        int jl = r / 8, e = r % 8;
        int j = c * 32 + jl;
        g_wxn[i] = Wih_f[(512 + j) * 8 + e];
    } else if (idx < N_WF + N_WXN + N_BIN) {
        int j = idx - N_WF - N_WXN;
        g_bin[j] = bih_f[512 + j];
    } else if (idx < N_PREP) {
        int i = idx - N_WF - N_WXN - N_BIN;
        int m = i / Hdim, j = i - m * Hdim;
        g_Wpt[i] = Wp[j * (2 * Hdim) + m];
    }
}

// ---------------- persistent GRU (no inter-CTA sync) ------------------------
__global__ void __launch_bounds__(THREADS, 1)
gru_persist(const float* __restrict__ x) {
    extern __shared__ unsigned smem[];
    const int tid  = threadIdx.x;
    const int bcta = blockIdx.x;        // rows 16*bcta .. 16*bcta+15

    // resident weights: slots 0..6 = chunks 0..6, slot 7 = x-fold chunk 16
    for (int i = tid; i < 49152; i += THREADS) {
        int cc = i / 6144, r = i % 6144;
        int s = r / 768, off = r - s * 768;
        int q = (s < 7) ? s : 16;
        smem[SW_RES + i] = g_wfrag[cc * 13056 + q * 768 + off];
    }
    for (int i = tid; i < 2048; i += THREADS)
        ((float*)(smem + SW_WXN))[i] = g_wxn[i];
    for (int i = tid; i < 256; i += THREADS)
        ((float*)(smem + SW_BIN))[i] = g_bin[i];
    for (int i = tid; i < 2048; i += THREADS)
        smem[SW_H + i] = 0u;            // parity-0 h = h(0) = 0
    // stage x(0) into xbuf[0] (warp 0)
    if (tid < 32) {
        const int prow = tid >> 1, phalf = tid & 1;
        float4 v = __ldg((const float4*)(x + (size_t)(bcta * 16 + prow) * (Wlen * Fin) + phalf * 4));
        *(float4*)((float*)(smem + SW_XB) + prow * 8 + phalf * 4) = v;
    }
    __syncthreads();

    const int w  = tid >> 5, L = tid & 31;
    const int c  = w >> 1;              // column group 0..7
    const int wc = w & 1;               // half (16 jl)
    const float* swxn = (const float*)(smem + SW_WXN);
    const float* sbin = (const float*)(smem + SW_BIN);
    const int resbase = c * 6144 + wc * 384;          // + slot*768 + nf*64 + 2L
    const unsigned* gW = g_wfrag + c * 13056 + wc * 384;

    float hold[8];
#pragma unroll
    for (int i = 0; i < 8; i++) hold[i] = 0.0f;

    for (int t = 0; t < Wlen; t++) {
        const int par = t & 1;
        const unsigned* hsrc = smem + SW_H + par * 2048;
        unsigned* hdst = smem + SW_H + (par ^ 1) * 2048;
        __syncthreads();    // h(t) + x(t) staged; old hdst/xbuf reads done

        float acc[6][4];
#pragma unroll
        for (int nf = 0; nf < 6; nf++)
#pragma unroll
            for (int u = 0; u < 4; u++) acc[nf][u] = 0.0f;

        // x(t) from SMEM stage: build x-fold A fragment (LDS, no exposure)
        const float* xb = (const float*)(smem + SW_XB) + par * 128;
        uint4 xfrag;
        {
            const int r0 = (L >> 2), c0 = (L & 3) << 1;
            float2 a = *(const float2*)(xb + r0 * 8 + c0);
            float2 b = *(const float2*)(xb + (r0 + 8) * 8 + c0);
            const unsigned one = ((L & 3) == 0) ? f2h2(1.0f, 0.0f) : 0u;
            xfrag.x = f2h2(a.x, a.y);
            xfrag.y = f2h2(b.x, b.y);
            xfrag.z = one;
            xfrag.w = one;
        }

        // warp 0: prefetch x(t+1) (latency covered by the whole MMA phase)
        float4 xnv = make_float4(0.f, 0.f, 0.f, 0.f);
        const bool pf = (tid < 32) && (t < Wlen - 1);
        if (pf) {
            const int prow = tid >> 1, phalf = tid & 1;
            xnv = __ldg((const float4*)(x + (size_t)(bcta * 16 + prow) * (Wlen * Fin)
                                          + (t + 1) * Fin + phalf * 4));
        }

        // issue ALL 4 initial streamed-B loads (chunks 7..10) up front
        uint2 Bs[4][6];
#pragma unroll
        for (int d = 0; d < 4; d++)
#pragma unroll
            for (int nf = 0; nf < 6; nf++)
                Bs[d][nf] = __ldcg((const uint2*)(gW + (7 + d) * 768 + nf * 64 + (L << 1)));

        // x-fold chunk (resident slot 7) — A in registers
        {
            const unsigned* bb = smem + resbase + 7 * 768 + (L << 1);
#pragma unroll
            for (int nf = 0; nf < 6; nf++) {
                uint2 bw = *(const uint2*)(bb + nf * 64);
                MMAH(acc[nf], xfrag, bw.x, bw.y);
            }
        }
        // resident h-chunks 0..6 (A from SMEM, B from SMEM)
#pragma unroll
        for (int q = 0; q < 7; q++) {
            uint4 af = *(const uint4*)(hsrc + q * 128 + (L << 2));
            const unsigned* bb = smem + resbase + q * 768 + (L << 1);
#pragma unroll
            for (int nf = 0; nf < 6; nf++) {
                uint2 bw = *(const uint2*)(bb + nf * 64);
                MMAH(acc[nf], af, bw.x, bw.y);
            }
        }
        // streamed h-chunks 7..15 (A from SMEM, B from depth-4 register ring)
#pragma unroll
        for (int d = 0; d < 9; d++) {
            const int q = 7 + d;
            const int s = d & 3;
            uint4 af = *(const uint4*)(hsrc + q * 128 + (L << 2));
#pragma unroll
            for (int nf = 0; nf < 6; nf++)
                MMAH(acc[nf], af, Bs[s][nf].x, Bs[s][nf].y);
            if (d + 4 < 9) {
#pragma unroll
                for (int nf = 0; nf < 6; nf++)
                    Bs[s][nf] = __ldcg((const uint2*)(gW + (q + 4) * 768 + nf * 64 + (L << 1)));
            }
        }

        // stage x(t+1) into the other xbuf (ordered by next step's sync)
        if (pf) {
            const int prow = tid >> 1, phalf = tid & 1;
            *(float4*)((float*)(smem + SW_XB) + (par ^ 1) * 128 + prow * 8 + phalf * 4) = xnv;
        }

        // ---- epilogue: inn (fp32, j-outer) + gates + h update + STS -------
        float x80[8], x81[8];
        {
            const float* xr0 = xb + (L >> 2) * 8;
            const float* xr1 = xb + ((L >> 2) + 8) * 8;
#pragma unroll
            for (int u = 0; u < 8; u++) { x80[u] = xr0[u]; x81[u] = xr1[u]; }
        }
        float hv[2][2][2];                 // [rh][fp][e]
#pragma unroll
        for (int fp = 0; fp < 2; fp++) {
#pragma unroll
            for (int e = 0; e < 2; e++) {
                const int jl = wc * 16 + 2 * (L & 3) + 8 * fp + e;
                const int j  = c * 32 + jl;
                const float* wj = swxn + j * 8;
                float xn0 = sbin[j], xn1 = sbin[j];
#pragma unroll
                for (int u = 0; u < 8; u++) {
                    xn0 = fmaf(x80[u], wj[u], xn0);
                    xn1 = fmaf(x81[u], wj[u], xn1);
                }
#pragma unroll
                for (int rh = 0; rh < 2; rh++) {
                    const int ci = rh * 2 + e;
                    float rp  = acc[fp][ci];          // bias+x folded via MMA
                    float zp  = acc[2 + fp][ci];
                    float hnv = acc[4 + fp][ci];      // includes bhn
                    float r = __fdividef(1.0f, 1.0f + __expf(-rp));
                    float z = __fdividef(1.0f, 1.0f + __expf(-zp));
                    float an = (rh ? xn1 : xn0) + r * hnv;
                    an = fminf(fmaxf(an, -15.0f), 15.0f);
                    float e2 = __expf(-2.0f * an);
                    float n  = (1.0f - e2) * __fdividef(1.0f, 1.0f + e2);
                    const int hidx = (rh * 2 + fp) * 2 + e;
                    float h = (1.0f - z) * n + z * hold[hidx];
                    hold[hidx] = h;
                    hv[rh][fp][e] = h;
                }
            }
        }
        unsigned whi[4];
#pragma unroll
        for (int rh = 0; rh < 2; rh++)
#pragma unroll
            for (int fp = 0; fp < 2; fp++)
                whi[rh + 2 * fp] = f2h2(hv[rh][fp][0], hv[rh][fp][1]);
        // warp w produces exactly chunk w
        *(uint4*)(hdst + w * 128 + (L << 2)) =
            make_uint4(whi[0], whi[1], whi[2], whi[3]);
    }

    // final h -> plain layout for the head
#pragma unroll
    for (int rh = 0; rh < 2; rh++) {
        const int row = bcta * 16 + (L >> 2) + 8 * rh;
#pragma unroll
        for (int fp = 0; fp < 2; fp++)
#pragma unroll
            for (int e = 0; e < 2; e++) {
                const int jl = wc * 16 + 2 * (L & 3) + 8 * fp + e;
                const int hidx = (rh * 2 + fp) * 2 + e;
                g_hfinal[(size_t)row * 256 + c * 32 + jl] = hold[hidx];
            }
    }
}

// ---------------- head: h_bwd + projection + GELU + LayerNorm ---------------
__global__ void __launch_bounds__(256)
head_kernel(const float* __restrict__ x,
            const float* __restrict__ Wih_b,
            const float* __restrict__ bih_b,
            const float* __restrict__ bhh_b,
            const float* __restrict__ bp,
            const float* __restrict__ gamma,
            const float* __restrict__ beta,
            float* __restrict__ out) {
    __shared__ float hf[8][Hdim];
    __shared__ float hb[8][Hdim];
    __shared__ float ys[8][Hdim];
    __shared__ float xs[8][Fin];

    const int tx = threadIdx.x;
    const int b0 = blockIdx.x * 8;

    for (int idx = tx; idx < 8 * Hdim; idx += 256) {
        int r = idx >> 8, k = idx & 255;
        hf[r][k] = g_hfinal[(size_t)(b0 + r) * Hdim + k];
    }
    if (tx < 64) {
        int r = tx >> 3, cc = tx & 7;
        xs[r][cc] = x[(size_t)(b0 + r) * (Wlen * Fin) + (Wlen - 1) * Fin + cc];
    }
    __syncthreads();

    {   // backward cell at h0 = 0
        const int j = tx;
        float wr[Fin], wz[Fin], wn[Fin];
#pragma unroll
        for (int cc = 0; cc < Fin; cc++) {
            wr[cc] = Wih_b[j * Fin + cc];
            wz[cc] = Wih_b[(256 + j) * Fin + cc];
            wn[cc] = Wih_b[(512 + j) * Fin + cc];
        }
        const float bir = bih_b[j],       bhr = bhh_b[j];
        const float biz = bih_b[256 + j], bhz = bhh_b[256 + j];
        const float bin = bih_b[512 + j], bhn = bhh_b[512 + j];
#pragma unroll
        for (int r8 = 0; r8 < 8; r8++) {
            float gr = bir + bhr, gz = biz + bhz, gn = bin;
#pragma unroll
            for (int cc = 0; cc < Fin; cc++) {
                float xvv = xs[r8][cc];
                gr = fmaf(xvv, wr[cc], gr);
                gz = fmaf(xvv, wz[cc], gz);
                gn = fmaf(xvv, wn[cc], gn);
            }
            float r = 1.0f / (1.0f + __expf(-gr));
            float z = 1.0f / (1.0f + __expf(-gz));
            float an = gn + r * bhn;
            an = fminf(fmaxf(an, -15.0f), 15.0f);
            float e = __expf(-2.0f * an);
            float n = (1.0f - e) / (1.0f + e);
            hb[r8][j] = (1.0f - z) * n;
        }
    }
    __syncthreads();

    {   // projection + exact GELU
        const int j = tx;
#pragma unroll
        for (int r8 = 0; r8 < 8; r8++) {
            float acc = bp[j];
#pragma unroll 4
            for (int k = 0; k < Hdim; k++)
                acc = fmaf(hf[r8][k], g_Wpt[k * Hdim + j], acc);
#pragma unroll 4
            for (int k = 0; k < Hdim; k++)
                acc = fmaf(hb[r8][k], g_Wpt[(Hdim + k) * Hdim + j], acc);
            ys[r8][j] = 0.5f * acc * (1.0f + erff(acc * 0.70710678118654752f));
        }
    }
    __syncthreads();

    const int w = tx >> 5, l = tx & 31;
    float s1 = 0.f, s2 = 0.f;
#pragma unroll
    for (int m = 0; m < 8; m++) {
        float v = ys[w][l + 32 * m];
        s1 += v; s2 += v * v;
    }
#pragma unroll
    for (int o = 16; o > 0; o >>= 1) {
        s1 += __shfl_xor_sync(0xffffffffu, s1, o);
        s2 += __shfl_xor_sync(0xffffffffu, s2, o);
    }
    const float mu  = s1 * (1.0f / 256.0f);
    const float var = s2 * (1.0f / 256.0f) - mu * mu;
    const float inv = rsqrtf(var + 1e-5f);
#pragma unroll
    for (int m = 0; m < 8; m++) {
        int col = l + 32 * m;
        float v = (ys[w][col] - mu) * inv;
        out[(size_t)(b0 + w) * Hdim + col] = v * gamma[col] + beta[col];
    }
}

// ---------------------------------------------------------------------------
extern "C" void kernel_launch(void* const* d_in, const int* in_sizes, int n_in,
                              void* d_out, int out_size) {
    const float* x     = (const float*)d_in[0];
    const float* Wih_f = (const float*)d_in[1];
    const float* Whh_f = (const float*)d_in[2];
    const float* bih_f = (const float*)d_in[3];
    const float* bhh_f = (const float*)d_in[4];
    const float* Wih_b = (const float*)d_in[5];
    /* Whh_b = d_in[6] unused: backward cell has h0 = 0 */
    const float* bih_b = (const float*)d_in[7];
    const float* bhh_b = (const float*)d_in[8];
    const float* Wp    = (const float*)d_in[9];
    const float* bp    = (const float*)d_in[10];
    const float* gamma = (const float*)d_in[11];
    const float* beta  = (const float*)d_in[12];
    float* out = (float*)d_out;

    cudaFuncSetAttribute(gru_persist, cudaFuncAttributeMaxDynamicSharedMemorySize, SM_TOTAL);

    prep_kernel<<<(N_PREP + 255) / 256, 256>>>(Whh_f, Wih_f, bih_f, bhh_f, Wp);
    gru_persist<<<Bsz / 16, THREADS, SM_TOTAL>>>(x);
    head_kernel<<<Bsz / 8, 256>>>(x, Wih_b, bih_b, bhh_b, bp, gamma, beta, out);
}